// round 5
// baseline (speedup 1.0000x reference)
#include <cuda_runtime.h>
#include <cuda_bf16.h>
#include <math.h>
#include <stdint.h>

#define BATCH   8
#define SEQ     2048
#define EMBED   1024
#define QKVD    3072

// ---------------- scratch (device globals; no allocs allowed) ---------------
__device__ float         g_V     [(size_t)BATCH * SEQ * EMBED];   // fp32 V
__device__ float         g_scores[(size_t)BATCH * SEQ * SEQ];
__device__ __nv_bfloat16 g_A1[(size_t)BATCH * SEQ * (3*EMBED)];   // x split  (A-order)
__device__ __nv_bfloat16 g_B1[(size_t)QKVD * (3*EMBED)];          // W split  (B-order)
__device__ __nv_bfloat16 g_QA[(size_t)BATCH * SEQ * (3*EMBED)];   // Q split  (A-order)
__device__ __nv_bfloat16 g_KB[(size_t)BATCH * SEQ * (3*EMBED)];   // K split  (B-order)
__device__ __nv_bfloat16 g_VB[(size_t)BATCH * EMBED * (3*SEQ)];   // V^T split (B-order)
__device__ __nv_bfloat16 g_PA[(size_t)BATCH * SEQ * (3*SEQ)];     // probs split (A-order)

// ---------------- asm helpers ------------------------------------------------
__device__ __forceinline__ uint32_t smem_u32(const void* p) {
    uint32_t a;
    asm("{ .reg .u64 t; cvta.to.shared.u64 t, %1; cvt.u32.u64 %0, t; }" : "=r"(a) : "l"(p));
    return a;
}
#define CP_ASYNC16(dst, src) \
    asm volatile("cp.async.cg.shared.global [%0], [%1], 16;" :: "r"(dst), "l"(src))
#define CP_COMMIT() asm volatile("cp.async.commit_group;" ::: "memory")
#define CP_WAIT2()  asm volatile("cp.async.wait_group 2;"  ::: "memory")
#define LDMX4(r, addr) \
    asm volatile("ldmatrix.sync.aligned.m8n8.x4.shared.b16 {%0,%1,%2,%3}, [%4];" \
        : "=r"((r)[0]), "=r"((r)[1]), "=r"((r)[2]), "=r"((r)[3]) : "r"(addr))
#define MMA16816(d, a, b) \
    asm volatile("mma.sync.aligned.m16n8k16.row.col.f32.bf16.bf16.f32 " \
        "{%0,%1,%2,%3}, {%4,%5,%6,%7}, {%8,%9}, {%0,%1,%2,%3};" \
        : "+f"((d)[0]), "+f"((d)[1]), "+f"((d)[2]), "+f"((d)[3]) \
        : "r"((a)[0]), "r"((a)[1]), "r"((a)[2]), "r"((a)[3]), "r"((b)[0]), "r"((b)[1]))

// ---------------- tensor-core GEMM -------------------------------------------
// C[m,n] = alpha * sum_k A[m,k] B[n,k]   (A, B row-major bf16, K-major)
// CTA tile 128x256, K-chunk 64, 3-stage cp.async pipeline.
// 256 threads = 8 warps (2m x 4n), warp tile 64x64, mma.m16n8k16 bf16->fp32.
// MODE 0: plain epilogue (alpha scale) -> fp32 C
// MODE 1: fused qkv epilogue (bias + per-region split to QA/KB/Vf)
#define LDT      72                      // smem row pitch in halves (144 B)
#define ATILE_H  (128 * LDT)             // A tile halves
#define BTILE_H  (256 * LDT)             // B tile halves
#define STAGE_H  (ATILE_H + BTILE_H)
#define NSTAGE   3
#define SMEM_B   (NSTAGE * STAGE_H * 2)  // 165888 bytes

__device__ __forceinline__ void load_chunk(uint32_t sb, int stage,
    const __nv_bfloat16* __restrict__ Ag, const __nv_bfloat16* __restrict__ Bg,
    int K, int k0, int tid)
{
    const uint32_t stbase = sb + (uint32_t)stage * (STAGE_H * 2);
    // A: 128 rows x 64 halves, 2 threads/row
    {
        const int r = tid >> 1;
        const int c = (tid & 1) * 32;
        const uint32_t base = stbase + (r * LDT + c) * 2;
        const __nv_bfloat16* as = Ag + (size_t)r * K + k0 + c;
        #pragma unroll
        for (int i = 0; i < 4; ++i) CP_ASYNC16(base + i * 16, as + i * 8);
    }
    // B: 256 rows x 64 halves, 1 thread/row
    {
        const int r = tid;
        const uint32_t base = stbase + ATILE_H * 2 + r * LDT * 2;
        const __nv_bfloat16* bs = Bg + (size_t)r * K + k0;
        #pragma unroll
        for (int i = 0; i < 8; ++i) CP_ASYNC16(base + i * 16, bs + i * 8);
    }
}

template<int MODE>
__global__ void __launch_bounds__(256, 1) mma_gemm(
    const __nv_bfloat16* __restrict__ A, const __nv_bfloat16* __restrict__ B,
    const float* __restrict__ bias, float* __restrict__ C,
    __nv_bfloat16* __restrict__ QA, __nv_bfloat16* __restrict__ KB,
    float* __restrict__ Vf,
    int K, int ldc, long long sA, long long sB, long long sC, float alpha)
{
    extern __shared__ char smem[];
    const uint32_t sb = smem_u32(smem);
    const int tid = threadIdx.x;
    const int lane = tid & 31;
    const int wid = tid >> 5;
    const int wm = (wid & 1) * 64;
    const int wn = (wid >> 1) * 64;

    const __nv_bfloat16* Ag = A + blockIdx.z * sA + (size_t)(blockIdx.y * 128) * K;
    const __nv_bfloat16* Bg = B + blockIdx.z * sB + (size_t)(blockIdx.x * 256) * K;

    const int ar = (lane & 7) + ((lane >> 3) & 1) * 8;
    const int ak = (lane >> 4) * 8;
    const int bn = (lane & 7) + ((lane >> 4) & 1) * 8;
    const int bk = ((lane >> 3) & 1) * 8;

    float acc[4][8][4];
    #pragma unroll
    for (int i = 0; i < 4; ++i)
        #pragma unroll
        for (int j = 0; j < 8; ++j)
            #pragma unroll
            for (int q = 0; q < 4; ++q) acc[i][j][q] = 0.0f;

    const int nch = K / 64;
    load_chunk(sb, 0, Ag, Bg, K, 0, tid);   CP_COMMIT();
    load_chunk(sb, 1, Ag, Bg, K, 64, tid);  CP_COMMIT();
    load_chunk(sb, 2, Ag, Bg, K, 128, tid); CP_COMMIT();

    int stage = 0;
    for (int ch = 0; ch < nch; ++ch) {
        CP_WAIT2();
        __syncthreads();

        const uint32_t abase = sb + (uint32_t)stage * (STAGE_H * 2);
        const uint32_t bbase = abase + ATILE_H * 2;
        #pragma unroll
        for (int s = 0; s < 4; ++s) {
            uint32_t a[4][4];
            #pragma unroll
            for (int mf = 0; mf < 4; ++mf)
                LDMX4(a[mf], abase + ((wm + mf * 16 + ar) * LDT + s * 16 + ak) * 2);
            uint32_t b[4][4];
            #pragma unroll
            for (int n2 = 0; n2 < 4; ++n2)
                LDMX4(b[n2], bbase + ((wn + n2 * 16 + bn) * LDT + s * 16 + bk) * 2);
            #pragma unroll
            for (int mf = 0; mf < 4; ++mf)
                #pragma unroll
                for (int nf = 0; nf < 8; ++nf)
                    MMA16816(acc[mf][nf], a[mf], &b[nf >> 1][(nf & 1) * 2]);
        }
        __syncthreads();
        if (ch + 3 < nch) load_chunk(sb, stage, Ag, Bg, K, (ch + 3) * 64, tid);
        CP_COMMIT();
        stage = (stage == NSTAGE - 1) ? 0 : stage + 1;
    }

    // ---------------- epilogue ----------------
    const int g  = lane >> 2;
    const int tg = lane & 3;

    if (MODE == 0) {
        float* Cg = C + blockIdx.z * sC;
        #pragma unroll
        for (int mf = 0; mf < 4; ++mf) {
            const int row0 = blockIdx.y * 128 + wm + mf * 16 + g;
            #pragma unroll
            for (int nf = 0; nf < 8; ++nf) {
                const int col = blockIdx.x * 256 + wn + nf * 8 + tg * 2;
                float2 v0 = make_float2(acc[mf][nf][0] * alpha, acc[mf][nf][1] * alpha);
                float2 v1 = make_float2(acc[mf][nf][2] * alpha, acc[mf][nf][3] * alpha);
                *reinterpret_cast<float2*>(Cg + (size_t)row0 * ldc + col) = v0;
                *reinterpret_cast<float2*>(Cg + (size_t)(row0 + 8) * ldc + col) = v1;
            }
        }
    } else {
        const int cblk = blockIdx.x * 256;
        const int region = cblk >> 10;               // 0=Q 1=K 2=V (256-slab within one region)
        #pragma unroll
        for (int mf = 0; mf < 4; ++mf) {
            const int row0 = blockIdx.y * 128 + wm + mf * 16 + g;
            #pragma unroll
            for (int nf = 0; nf < 8; ++nf) {
                const int gcol = cblk + wn + nf * 8 + tg * 2;
                const float2 bb = *reinterpret_cast<const float2*>(bias + gcol);
                float v[2][2];
                v[0][0] = acc[mf][nf][0] + bb.x;  v[0][1] = acc[mf][nf][1] + bb.y;
                v[1][0] = acc[mf][nf][2] + bb.x;  v[1][1] = acc[mf][nf][3] + bb.y;
                const int lcol = gcol & 1023;
                if (region == 2) {
                    *reinterpret_cast<float2*>(Vf + (size_t)row0 * EMBED + lcol)
                        = make_float2(v[0][0], v[0][1]);
                    *reinterpret_cast<float2*>(Vf + (size_t)(row0 + 8) * EMBED + lcol)
                        = make_float2(v[1][0], v[1][1]);
                } else {
                    __nv_bfloat16* dst = (region == 0) ? QA : KB;
                    #pragma unroll
                    for (int h = 0; h < 2; ++h) {
                        const int r = row0 + h * 8;
                        __nv_bfloat16 hi0 = __float2bfloat16(v[h][0]);
                        __nv_bfloat16 hi1 = __float2bfloat16(v[h][1]);
                        __nv_bfloat16 lo0 = __float2bfloat16(v[h][0] - __bfloat162float(hi0));
                        __nv_bfloat16 lo1 = __float2bfloat16(v[h][1] - __bfloat162float(hi1));
                        __nv_bfloat162 hp(hi0, hi1), lp(lo0, lo1);
                        __nv_bfloat16* d0 = dst + (size_t)r * (3 * EMBED) + lcol;
                        if (region == 0) {   // QA: hi | lo | hi
                            *reinterpret_cast<__nv_bfloat162*>(d0)             = hp;
                            *reinterpret_cast<__nv_bfloat162*>(d0 + EMBED)     = lp;
                            *reinterpret_cast<__nv_bfloat162*>(d0 + 2 * EMBED) = hp;
                        } else {             // KB: hi | hi | lo
                            *reinterpret_cast<__nv_bfloat162*>(d0)             = hp;
                            *reinterpret_cast<__nv_bfloat162*>(d0 + EMBED)     = hp;
                            *reinterpret_cast<__nv_bfloat162*>(d0 + 2 * EMBED) = lp;
                        }
                    }
                }
            }
        }
    }
}

// ---------------- fp32 -> bf16 hi/lo split (for x and W inputs) --------------
template<bool AORDER>
__global__ void split_kernel(const float* __restrict__ src, __nv_bfloat16* __restrict__ dst,
                             int K, int srcPitch, int srcOff, long long nvec)
{
    long long i = blockIdx.x * (long long)blockDim.x + threadIdx.x;
    if (i >= nvec) return;
    long long e = i * 4;
    int row = (int)(e / K), col = (int)(e % K);
    const float4 v = *reinterpret_cast<const float4*>(src + (size_t)row * srcPitch + srcOff + col);
    float vs[4] = { v.x, v.y, v.z, v.w };
    __nv_bfloat16 h[4], l[4];
    #pragma unroll
    for (int j = 0; j < 4; ++j) {
        h[j] = __float2bfloat16(vs[j]);
        l[j] = __float2bfloat16(vs[j] - __bfloat162float(h[j]));
    }
    __nv_bfloat162 hp0(h[0], h[1]), hp1(h[2], h[3]);
    __nv_bfloat162 lp0(l[0], l[1]), lp1(l[2], l[3]);
    __nv_bfloat16* d0 = dst + (size_t)row * 3 * K + col;
    reinterpret_cast<__nv_bfloat162*>(d0)[0] = hp0;
    reinterpret_cast<__nv_bfloat162*>(d0)[1] = hp1;
    if (AORDER) {
        reinterpret_cast<__nv_bfloat162*>(d0 + K)[0] = lp0;
        reinterpret_cast<__nv_bfloat162*>(d0 + K)[1] = lp1;
        reinterpret_cast<__nv_bfloat162*>(d0 + 2 * K)[0] = hp0;
        reinterpret_cast<__nv_bfloat162*>(d0 + 2 * K)[1] = hp1;
    } else {
        reinterpret_cast<__nv_bfloat162*>(d0 + K)[0] = hp0;
        reinterpret_cast<__nv_bfloat162*>(d0 + K)[1] = hp1;
        reinterpret_cast<__nv_bfloat162*>(d0 + 2 * K)[0] = lp0;
        reinterpret_cast<__nv_bfloat162*>(d0 + 2 * K)[1] = lp1;
    }
}

// ---------------- V transpose + split (B-order [hi|hi|lo]) -------------------
__global__ void vtrans_kernel(const float* __restrict__ Vf, __nv_bfloat16* __restrict__ VB)
{
    __shared__ float t[32][33];
    const int b = blockIdx.z;
    const int n0 = blockIdx.x * 32, e0 = blockIdx.y * 32;
    const int tx = threadIdx.x, ty = threadIdx.y;
    const float* src = Vf + (size_t)b * SEQ * EMBED;
    #pragma unroll
    for (int i = 0; i < 4; ++i)
        t[ty + 8 * i][tx] = src[(size_t)(n0 + ty + 8 * i) * EMBED + e0 + tx];
    __syncthreads();
    __nv_bfloat16* dst = VB + (size_t)b * EMBED * (3 * SEQ);
    #pragma unroll
    for (int i = 0; i < 4; ++i) {
        const float v = t[tx][ty + 8 * i];
        const __nv_bfloat16 h = __float2bfloat16(v);
        const __nv_bfloat16 l = __float2bfloat16(v - __bfloat162float(h));
        const size_t base = (size_t)(e0 + ty + 8 * i) * (3 * SEQ) + n0 + tx;
        dst[base]           = h;
        dst[base + SEQ]     = h;
        dst[base + 2 * SEQ] = l;
    }
}

// ---------------- softmax + prob split (A-order [hi|lo|hi]) ------------------
__global__ void softmax_pa_kernel(const float* __restrict__ s, __nv_bfloat16* __restrict__ PA)
{
    __shared__ float row[SEQ];
    __shared__ float red[8];
    const int tid = threadIdx.x;
    const float4* p4 = reinterpret_cast<const float4*>(s + (size_t)blockIdx.x * SEQ);
    float4* r4 = reinterpret_cast<float4*>(row);

    float lmax = -3.4e38f;
    #pragma unroll
    for (int it = 0; it < 2; ++it) {
        const float4 t = p4[tid + it * 256];
        r4[tid + it * 256] = t;
        lmax = fmaxf(lmax, fmaxf(fmaxf(t.x, t.y), fmaxf(t.z, t.w)));
    }
    #pragma unroll
    for (int o = 16; o; o >>= 1) lmax = fmaxf(lmax, __shfl_xor_sync(0xffffffffu, lmax, o));
    if ((tid & 31) == 0) red[tid >> 5] = lmax;
    __syncthreads();
    const float rmax = fmaxf(fmaxf(fmaxf(red[0], red[1]), fmaxf(red[2], red[3])),
                             fmaxf(fmaxf(red[4], red[5]), fmaxf(red[6], red[7])));
    __syncthreads();

    float lsum = 0.0f;
    #pragma unroll
    for (int it = 0; it < 2; ++it) {
        float4 t = r4[tid + it * 256];
        t.x = expf(t.x - rmax); t.y = expf(t.y - rmax);
        t.z = expf(t.z - rmax); t.w = expf(t.w - rmax);
        r4[tid + it * 256] = t;
        lsum += (t.x + t.y) + (t.z + t.w);
    }
    #pragma unroll
    for (int o = 16; o; o >>= 1) lsum += __shfl_xor_sync(0xffffffffu, lsum, o);
    if ((tid & 31) == 0) red[tid >> 5] = lsum;
    __syncthreads();
    const float inv = 1.0f / (((red[0] + red[1]) + (red[2] + red[3])) +
                              ((red[4] + red[5]) + (red[6] + red[7])));

    __nv_bfloat16* pa = PA + (size_t)blockIdx.x * (3 * SEQ);
    #pragma unroll
    for (int it = 0; it < 2; ++it) {
        float4 t = r4[tid + it * 256];
        t.x *= inv; t.y *= inv; t.z *= inv; t.w *= inv;
        float vs[4] = { t.x, t.y, t.z, t.w };
        __nv_bfloat16 h[4], l[4];
        #pragma unroll
        for (int j = 0; j < 4; ++j) {
            h[j] = __float2bfloat16(vs[j]);
            l[j] = __float2bfloat16(vs[j] - __bfloat162float(h[j]));
        }
        const int idx = (tid + it * 256) * 4;
        __nv_bfloat162 hp0(h[0], h[1]), hp1(h[2], h[3]);
        __nv_bfloat162 lp0(l[0], l[1]), lp1(l[2], l[3]);
        reinterpret_cast<__nv_bfloat162*>(pa + idx)[0] = hp0;
        reinterpret_cast<__nv_bfloat162*>(pa + idx)[1] = hp1;
        reinterpret_cast<__nv_bfloat162*>(pa + SEQ + idx)[0] = lp0;
        reinterpret_cast<__nv_bfloat162*>(pa + SEQ + idx)[1] = lp1;
        reinterpret_cast<__nv_bfloat162*>(pa + 2 * SEQ + idx)[0] = hp0;
        reinterpret_cast<__nv_bfloat162*>(pa + 2 * SEQ + idx)[1] = hp1;
    }
}

// -----------------------------------------------------------------------------
extern "C" void kernel_launch(void* const* d_in, const int* in_sizes, int n_in,
                              void* d_out, int out_size)
{
    const float* x = (const float*)d_in[0];
    const float* W = (const float*)d_in[1];
    const float* b = (const float*)d_in[2];
    float* out = (float*)d_out;

    float *Vf, *sc;
    __nv_bfloat16 *A1, *B1, *QA, *KB, *VB, *PA;
    { void* p; cudaGetSymbolAddress(&p, g_V);      Vf = (float*)p; }
    { void* p; cudaGetSymbolAddress(&p, g_scores); sc = (float*)p; }
    { void* p; cudaGetSymbolAddress(&p, g_A1); A1 = (__nv_bfloat16*)p; }
    { void* p; cudaGetSymbolAddress(&p, g_B1); B1 = (__nv_bfloat16*)p; }
    { void* p; cudaGetSymbolAddress(&p, g_QA); QA = (__nv_bfloat16*)p; }
    { void* p; cudaGetSymbolAddress(&p, g_KB); KB = (__nv_bfloat16*)p; }
    { void* p; cudaGetSymbolAddress(&p, g_VB); VB = (__nv_bfloat16*)p; }
    { void* p; cudaGetSymbolAddress(&p, g_PA); PA = (__nv_bfloat16*)p; }

    cudaFuncSetAttribute(mma_gemm<0>, cudaFuncAttributeMaxDynamicSharedMemorySize, SMEM_B);
    cudaFuncSetAttribute(mma_gemm<1>, cudaFuncAttributeMaxDynamicSharedMemorySize, SMEM_B);

    const long long MN = (long long)BATCH * SEQ;   // 16384

    // input splits: x -> A1 (A-order), W -> B1 (B-order)
    split_kernel<true ><<<(unsigned)((MN * EMBED / 4 + 255) / 256), 256>>>(
        x, A1, EMBED, EMBED, 0, MN * EMBED / 4);
    split_kernel<false><<<(unsigned)(((long long)QKVD * EMBED / 4 + 255) / 256), 256>>>(
        W, B1, EMBED, EMBED, 0, (long long)QKVD * EMBED / 4);

    // GEMM1 (fused): qkv = x @ W^T + b, epilogue emits QA / KB / Vf directly
    mma_gemm<1><<<dim3(QKVD / 256, (unsigned)(MN / 128), 1), 256, SMEM_B>>>(
        A1, B1, b, nullptr, QA, KB, Vf,
        3 * EMBED, 0, 0, 0, 0, 1.0f);

    // V transpose + split
    vtrans_kernel<<<dim3(SEQ / 32, EMBED / 32, BATCH), dim3(32, 8)>>>(Vf, VB);

    // GEMM2: scores = Q @ K^T / 32   (per batch M=N=2048, Keff=3072)
    mma_gemm<0><<<dim3(SEQ / 256, SEQ / 128, BATCH), 256, SMEM_B>>>(
        QA, KB, nullptr, sc, nullptr, nullptr, nullptr,
        3 * EMBED, SEQ,
        (long long)SEQ * 3 * EMBED, (long long)SEQ * 3 * EMBED, (long long)SEQ * SEQ,
        0.03125f);

    // softmax + split -> PA
    softmax_pa_kernel<<<BATCH * SEQ, 256>>>(sc, PA);

    // GEMM3: out = P @ V   (per batch M=2048, N=1024, Keff=6144)
    mma_gemm<0><<<dim3(EMBED / 256, SEQ / 128, BATCH), 256, SMEM_B>>>(
        PA, VB, nullptr, out, nullptr, nullptr, nullptr,
        3 * SEQ, EMBED,
        (long long)SEQ * 3 * SEQ, (long long)EMBED * 3 * SEQ, (long long)SEQ * EMBED,
        1.0f);
}

// round 6
// speedup vs baseline: 1.1195x; 1.1195x over previous
#include <cuda_runtime.h>
#include <cuda_bf16.h>
#include <math.h>
#include <stdint.h>

#define BATCH   8
#define SEQ     2048
#define EMBED   1024
#define QKVD    3072

// ---------------- scratch (device globals; no allocs allowed) ---------------
__device__ float         g_V     [(size_t)BATCH * SEQ * EMBED];   // fp32 V
__device__ float         g_scores[(size_t)BATCH * SEQ * SEQ];
__device__ __nv_bfloat16 g_A1[(size_t)BATCH * SEQ * (3*EMBED)];   // x split  (A-order)
__device__ __nv_bfloat16 g_B1[(size_t)QKVD * (3*EMBED)];          // W split  (B-order)
__device__ __nv_bfloat16 g_QA[(size_t)BATCH * SEQ * (3*EMBED)];   // Q split  (A-order)
__device__ __nv_bfloat16 g_KB[(size_t)BATCH * SEQ * (3*EMBED)];   // K split  (B-order)
__device__ __nv_bfloat16 g_VB[(size_t)BATCH * EMBED * (3*SEQ)];   // V^T split (B-order)
__device__ __nv_bfloat16 g_PA[(size_t)BATCH * SEQ * (3*SEQ)];     // probs split (A-order)

// ---------------- asm helpers ------------------------------------------------
__device__ __forceinline__ uint32_t smem_u32(const void* p) {
    uint32_t a;
    asm("{ .reg .u64 t; cvta.to.shared.u64 t, %1; cvt.u32.u64 %0, t; }" : "=r"(a) : "l"(p));
    return a;
}
#define CP_ASYNC16(dst, src) \
    asm volatile("cp.async.cg.shared.global [%0], [%1], 16;" :: "r"(dst), "l"(src))
#define CP_COMMIT() asm volatile("cp.async.commit_group;" ::: "memory")
#define CP_WAIT1()  asm volatile("cp.async.wait_group 1;"  ::: "memory")
#define LDMX4(r, addr) \
    asm volatile("ldmatrix.sync.aligned.m8n8.x4.shared.b16 {%0,%1,%2,%3}, [%4];" \
        : "=r"((r)[0]), "=r"((r)[1]), "=r"((r)[2]), "=r"((r)[3]) : "r"(addr))
#define MMA16816(d, a, b) \
    asm volatile("mma.sync.aligned.m16n8k16.row.col.f32.bf16.bf16.f32 " \
        "{%0,%1,%2,%3}, {%4,%5,%6,%7}, {%8,%9}, {%0,%1,%2,%3};" \
        : "+f"((d)[0]), "+f"((d)[1]), "+f"((d)[2]), "+f"((d)[3]) \
        : "r"((a)[0]), "r"((a)[1]), "r"((a)[2]), "r"((a)[3]), "r"((b)[0]), "r"((b)[1]))

// ---------------- tensor-core GEMM -------------------------------------------
// C[m,n] = alpha * sum_k A[m,k] B[n,k]   (A, B row-major bf16, K-major)
// CTA tile 128x128, K-chunk 64, 3-stage cp.async, single-sync multistage loop.
// 256 threads = 8 warps (2m x 4n), warp tile 64x32, mma.m16n8k16 bf16->fp32.
// MODE 0: plain epilogue (alpha scale) -> fp32 C
// MODE 1: fused qkv epilogue (bias + per-region split to QA/KB/Vf)
#define LDT     72                       // smem row pitch in halves (144 B)
#define ATILE_H (128 * LDT)
#define STAGE_H (2 * ATILE_H)            // A+B tile per stage (halves)
#define NSTAGE  3
#define SMEM_B  (NSTAGE * STAGE_H * 2)   // 110592 bytes

__device__ __forceinline__ void load_chunk(uint32_t sb, int stage,
    const __nv_bfloat16* __restrict__ Ag, const __nv_bfloat16* __restrict__ Bg,
    int K, int k0, int tid)
{
    const int r = tid >> 1;
    const int c = (tid & 1) * 32;
    const uint32_t base = sb + (uint32_t)stage * (STAGE_H * 2) + (r * LDT + c) * 2;
    const __nv_bfloat16* as = Ag + (size_t)r * K + k0 + c;
    const __nv_bfloat16* bs = Bg + (size_t)r * K + k0 + c;
    #pragma unroll
    for (int i = 0; i < 4; ++i) CP_ASYNC16(base + i * 16, as + i * 8);
    #pragma unroll
    for (int i = 0; i < 4; ++i) CP_ASYNC16(base + ATILE_H * 2 + i * 16, bs + i * 8);
}

template<int MODE>
__global__ void __launch_bounds__(256, 2) mma_gemm(
    const __nv_bfloat16* __restrict__ A, const __nv_bfloat16* __restrict__ B,
    const float* __restrict__ bias, float* __restrict__ C,
    __nv_bfloat16* __restrict__ QA, __nv_bfloat16* __restrict__ KB,
    float* __restrict__ Vf,
    int K, int ldc, long long sA, long long sB, long long sC, float alpha)
{
    extern __shared__ char smem[];
    const uint32_t sb = smem_u32(smem);
    const int tid = threadIdx.x;
    const int lane = tid & 31;
    const int wid = tid >> 5;
    const int wm = (wid & 1) * 64;
    const int wn = (wid >> 1) * 32;

    const __nv_bfloat16* Ag = A + blockIdx.z * sA + (size_t)(blockIdx.y * 128) * K;
    const __nv_bfloat16* Bg = B + blockIdx.z * sB + (size_t)(blockIdx.x * 128) * K;

    const int ar = (lane & 7) + ((lane >> 3) & 1) * 8;
    const int ak = (lane >> 4) * 8;
    const int bn = (lane & 7) + ((lane >> 4) & 1) * 8;
    const int bk = ((lane >> 3) & 1) * 8;

    float acc[4][4][4];
    #pragma unroll
    for (int i = 0; i < 4; ++i)
        #pragma unroll
        for (int j = 0; j < 4; ++j)
            #pragma unroll
            for (int q = 0; q < 4; ++q) acc[i][j][q] = 0.0f;

    const int nch = K / 64;
    load_chunk(sb, 0, Ag, Bg, K, 0, tid);  CP_COMMIT();
    load_chunk(sb, 1, Ag, Bg, K, 64, tid); CP_COMMIT();

    for (int ch = 0; ch < nch; ++ch) {
        const int stage = ch % NSTAGE;
        CP_WAIT1();              // chunk ch resident
        __syncthreads();         // publish cp.async writes; free stage (ch-1)%3

        // issue loads for chunk ch+2 into stage (ch+2)%3 == (ch-1)%3 (freed above)
        if (ch + 2 < nch) load_chunk(sb, (ch + 2) % NSTAGE, Ag, Bg, K, (ch + 2) * 64, tid);
        CP_COMMIT();             // one group per iteration keeps wait_group accounting

        const uint32_t abase = sb + (uint32_t)stage * (STAGE_H * 2);
        const uint32_t bbase = abase + ATILE_H * 2;
        #pragma unroll
        for (int s = 0; s < 4; ++s) {
            uint32_t a[4][4];
            #pragma unroll
            for (int mf = 0; mf < 4; ++mf)
                LDMX4(a[mf], abase + ((wm + mf * 16 + ar) * LDT + s * 16 + ak) * 2);
            uint32_t b[2][4];
            #pragma unroll
            for (int n2 = 0; n2 < 2; ++n2)
                LDMX4(b[n2], bbase + ((wn + n2 * 16 + bn) * LDT + s * 16 + bk) * 2);
            #pragma unroll
            for (int mf = 0; mf < 4; ++mf)
                #pragma unroll
                for (int nf = 0; nf < 4; ++nf)
                    MMA16816(acc[mf][nf], a[mf], &b[nf >> 1][(nf & 1) * 2]);
        }
    }

    // ---------------- epilogue ----------------
    const int g  = lane >> 2;
    const int tg = lane & 3;

    if (MODE == 0) {
        float* Cg = C + blockIdx.z * sC;
        #pragma unroll
        for (int mf = 0; mf < 4; ++mf) {
            const int row0 = blockIdx.y * 128 + wm + mf * 16 + g;
            #pragma unroll
            for (int nf = 0; nf < 4; ++nf) {
                const int col = blockIdx.x * 128 + wn + nf * 8 + tg * 2;
                float2 v0 = make_float2(acc[mf][nf][0] * alpha, acc[mf][nf][1] * alpha);
                float2 v1 = make_float2(acc[mf][nf][2] * alpha, acc[mf][nf][3] * alpha);
                *reinterpret_cast<float2*>(Cg + (size_t)row0 * ldc + col) = v0;
                *reinterpret_cast<float2*>(Cg + (size_t)(row0 + 8) * ldc + col) = v1;
            }
        }
    } else {
        const int cblk = blockIdx.x * 128;
        const int region = cblk >> 10;               // 0=Q 1=K 2=V
        #pragma unroll
        for (int mf = 0; mf < 4; ++mf) {
            const int row0 = blockIdx.y * 128 + wm + mf * 16 + g;
            #pragma unroll
            for (int nf = 0; nf < 4; ++nf) {
                const int gcol = cblk + wn + nf * 8 + tg * 2;
                const float2 bb = *reinterpret_cast<const float2*>(bias + gcol);
                float v[2][2];
                v[0][0] = acc[mf][nf][0] + bb.x;  v[0][1] = acc[mf][nf][1] + bb.y;
                v[1][0] = acc[mf][nf][2] + bb.x;  v[1][1] = acc[mf][nf][3] + bb.y;
                const int lcol = gcol & 1023;
                if (region == 2) {
                    *reinterpret_cast<float2*>(Vf + (size_t)row0 * EMBED + lcol)
                        = make_float2(v[0][0], v[0][1]);
                    *reinterpret_cast<float2*>(Vf + (size_t)(row0 + 8) * EMBED + lcol)
                        = make_float2(v[1][0], v[1][1]);
                } else {
                    __nv_bfloat16* dst = (region == 0) ? QA : KB;
                    #pragma unroll
                    for (int h = 0; h < 2; ++h) {
                        const int r = row0 + h * 8;
                        __nv_bfloat16 hi0 = __float2bfloat16(v[h][0]);
                        __nv_bfloat16 hi1 = __float2bfloat16(v[h][1]);
                        __nv_bfloat16 lo0 = __float2bfloat16(v[h][0] - __bfloat162float(hi0));
                        __nv_bfloat16 lo1 = __float2bfloat16(v[h][1] - __bfloat162float(hi1));
                        __nv_bfloat162 hp(hi0, hi1), lp(lo0, lo1);
                        __nv_bfloat16* d0 = dst + (size_t)r * (3 * EMBED) + lcol;
                        if (region == 0) {   // QA: hi | lo | hi
                            *reinterpret_cast<__nv_bfloat162*>(d0)             = hp;
                            *reinterpret_cast<__nv_bfloat162*>(d0 + EMBED)     = lp;
                            *reinterpret_cast<__nv_bfloat162*>(d0 + 2 * EMBED) = hp;
                        } else {             // KB: hi | hi | lo
                            *reinterpret_cast<__nv_bfloat162*>(d0)             = hp;
                            *reinterpret_cast<__nv_bfloat162*>(d0 + EMBED)     = hp;
                            *reinterpret_cast<__nv_bfloat162*>(d0 + 2 * EMBED) = lp;
                        }
                    }
                }
            }
        }
    }
}

// ---------------- fp32 -> bf16 hi/lo split (for x and W inputs) --------------
template<bool AORDER>
__global__ void split_kernel(const float* __restrict__ src, __nv_bfloat16* __restrict__ dst,
                             int K, int srcPitch, int srcOff, long long nvec)
{
    long long i = blockIdx.x * (long long)blockDim.x + threadIdx.x;
    if (i >= nvec) return;
    long long e = i * 4;
    int row = (int)(e / K), col = (int)(e % K);
    const float4 v = *reinterpret_cast<const float4*>(src + (size_t)row * srcPitch + srcOff + col);
    float vs[4] = { v.x, v.y, v.z, v.w };
    __nv_bfloat16 h[4], l[4];
    #pragma unroll
    for (int j = 0; j < 4; ++j) {
        h[j] = __float2bfloat16(vs[j]);
        l[j] = __float2bfloat16(vs[j] - __bfloat162float(h[j]));
    }
    __nv_bfloat162 hp0(h[0], h[1]), hp1(h[2], h[3]);
    __nv_bfloat162 lp0(l[0], l[1]), lp1(l[2], l[3]);
    __nv_bfloat16* d0 = dst + (size_t)row * 3 * K + col;
    reinterpret_cast<__nv_bfloat162*>(d0)[0] = hp0;
    reinterpret_cast<__nv_bfloat162*>(d0)[1] = hp1;
    if (AORDER) {
        reinterpret_cast<__nv_bfloat162*>(d0 + K)[0] = lp0;
        reinterpret_cast<__nv_bfloat162*>(d0 + K)[1] = lp1;
        reinterpret_cast<__nv_bfloat162*>(d0 + 2 * K)[0] = hp0;
        reinterpret_cast<__nv_bfloat162*>(d0 + 2 * K)[1] = hp1;
    } else {
        reinterpret_cast<__nv_bfloat162*>(d0 + K)[0] = hp0;
        reinterpret_cast<__nv_bfloat162*>(d0 + K)[1] = hp1;
        reinterpret_cast<__nv_bfloat162*>(d0 + 2 * K)[0] = lp0;
        reinterpret_cast<__nv_bfloat162*>(d0 + 2 * K)[1] = lp1;
    }
}

// ---------------- V transpose + split (B-order [hi|hi|lo]) -------------------
__global__ void vtrans_kernel(const float* __restrict__ Vf, __nv_bfloat16* __restrict__ VB)
{
    __shared__ float t[32][33];
    const int b = blockIdx.z;
    const int n0 = blockIdx.x * 32, e0 = blockIdx.y * 32;
    const int tx = threadIdx.x, ty = threadIdx.y;
    const float* src = Vf + (size_t)b * SEQ * EMBED;
    #pragma unroll
    for (int i = 0; i < 4; ++i)
        t[ty + 8 * i][tx] = src[(size_t)(n0 + ty + 8 * i) * EMBED + e0 + tx];
    __syncthreads();
    __nv_bfloat16* dst = VB + (size_t)b * EMBED * (3 * SEQ);
    #pragma unroll
    for (int i = 0; i < 4; ++i) {
        const float v = t[tx][ty + 8 * i];
        const __nv_bfloat16 h = __float2bfloat16(v);
        const __nv_bfloat16 l = __float2bfloat16(v - __bfloat162float(h));
        const size_t base = (size_t)(e0 + ty + 8 * i) * (3 * SEQ) + n0 + tx;
        dst[base]           = h;
        dst[base + SEQ]     = h;
        dst[base + 2 * SEQ] = l;
    }
}

// ---------------- softmax + prob split (A-order [hi|lo|hi]) ------------------
__global__ void softmax_pa_kernel(const float* __restrict__ s, __nv_bfloat16* __restrict__ PA)
{
    __shared__ float row[SEQ];
    __shared__ float red[8];
    const int tid = threadIdx.x;
    const float4* p4 = reinterpret_cast<const float4*>(s + (size_t)blockIdx.x * SEQ);
    float4* r4 = reinterpret_cast<float4*>(row);

    float lmax = -3.4e38f;
    #pragma unroll
    for (int it = 0; it < 2; ++it) {
        const float4 t = p4[tid + it * 256];
        r4[tid + it * 256] = t;
        lmax = fmaxf(lmax, fmaxf(fmaxf(t.x, t.y), fmaxf(t.z, t.w)));
    }
    #pragma unroll
    for (int o = 16; o; o >>= 1) lmax = fmaxf(lmax, __shfl_xor_sync(0xffffffffu, lmax, o));
    if ((tid & 31) == 0) red[tid >> 5] = lmax;
    __syncthreads();
    const float rmax = fmaxf(fmaxf(fmaxf(red[0], red[1]), fmaxf(red[2], red[3])),
                             fmaxf(fmaxf(red[4], red[5]), fmaxf(red[6], red[7])));
    __syncthreads();

    float lsum = 0.0f;
    #pragma unroll
    for (int it = 0; it < 2; ++it) {
        float4 t = r4[tid + it * 256];
        t.x = expf(t.x - rmax); t.y = expf(t.y - rmax);
        t.z = expf(t.z - rmax); t.w = expf(t.w - rmax);
        r4[tid + it * 256] = t;
        lsum += (t.x + t.y) + (t.z + t.w);
    }
    #pragma unroll
    for (int o = 16; o; o >>= 1) lsum += __shfl_xor_sync(0xffffffffu, lsum, o);
    if ((tid & 31) == 0) red[tid >> 5] = lsum;
    __syncthreads();
    const float inv = 1.0f / (((red[0] + red[1]) + (red[2] + red[3])) +
                              ((red[4] + red[5]) + (red[6] + red[7])));

    __nv_bfloat16* pa = PA + (size_t)blockIdx.x * (3 * SEQ);
    #pragma unroll
    for (int it = 0; it < 2; ++it) {
        float4 t = r4[tid + it * 256];
        t.x *= inv; t.y *= inv; t.z *= inv; t.w *= inv;
        float vs[4] = { t.x, t.y, t.z, t.w };
        __nv_bfloat16 h[4], l[4];
        #pragma unroll
        for (int j = 0; j < 4; ++j) {
            h[j] = __float2bfloat16(vs[j]);
            l[j] = __float2bfloat16(vs[j] - __bfloat162float(h[j]));
        }
        const int idx = (tid + it * 256) * 4;
        __nv_bfloat162 hp0(h[0], h[1]), hp1(h[2], h[3]);
        __nv_bfloat162 lp0(l[0], l[1]), lp1(l[2], l[3]);
        reinterpret_cast<__nv_bfloat162*>(pa + idx)[0] = hp0;
        reinterpret_cast<__nv_bfloat162*>(pa + idx)[1] = hp1;
        reinterpret_cast<__nv_bfloat162*>(pa + SEQ + idx)[0] = lp0;
        reinterpret_cast<__nv_bfloat162*>(pa + SEQ + idx)[1] = lp1;
        reinterpret_cast<__nv_bfloat162*>(pa + 2 * SEQ + idx)[0] = hp0;
        reinterpret_cast<__nv_bfloat162*>(pa + 2 * SEQ + idx)[1] = hp1;
    }
}

// -----------------------------------------------------------------------------
extern "C" void kernel_launch(void* const* d_in, const int* in_sizes, int n_in,
                              void* d_out, int out_size)
{
    const float* x = (const float*)d_in[0];
    const float* W = (const float*)d_in[1];
    const float* b = (const float*)d_in[2];
    float* out = (float*)d_out;

    float *Vf, *sc;
    __nv_bfloat16 *A1, *B1, *QA, *KB, *VB, *PA;
    { void* p; cudaGetSymbolAddress(&p, g_V);      Vf = (float*)p; }
    { void* p; cudaGetSymbolAddress(&p, g_scores); sc = (float*)p; }
    { void* p; cudaGetSymbolAddress(&p, g_A1); A1 = (__nv_bfloat16*)p; }
    { void* p; cudaGetSymbolAddress(&p, g_B1); B1 = (__nv_bfloat16*)p; }
    { void* p; cudaGetSymbolAddress(&p, g_QA); QA = (__nv_bfloat16*)p; }
    { void* p; cudaGetSymbolAddress(&p, g_KB); KB = (__nv_bfloat16*)p; }
    { void* p; cudaGetSymbolAddress(&p, g_VB); VB = (__nv_bfloat16*)p; }
    { void* p; cudaGetSymbolAddress(&p, g_PA); PA = (__nv_bfloat16*)p; }

    cudaFuncSetAttribute(mma_gemm<0>, cudaFuncAttributeMaxDynamicSharedMemorySize, SMEM_B);
    cudaFuncSetAttribute(mma_gemm<1>, cudaFuncAttributeMaxDynamicSharedMemorySize, SMEM_B);

    const long long MN = (long long)BATCH * SEQ;   // 16384

    // input splits: x -> A1 (A-order), W -> B1 (B-order)
    split_kernel<true ><<<(unsigned)((MN * EMBED / 4 + 255) / 256), 256>>>(
        x, A1, EMBED, EMBED, 0, MN * EMBED / 4);
    split_kernel<false><<<(unsigned)(((long long)QKVD * EMBED / 4 + 255) / 256), 256>>>(
        W, B1, EMBED, EMBED, 0, (long long)QKVD * EMBED / 4);

    // GEMM1 (fused): qkv = x @ W^T + b, epilogue emits QA / KB / Vf directly
    mma_gemm<1><<<dim3(QKVD / 128, (unsigned)(MN / 128), 1), 256, SMEM_B>>>(
        A1, B1, b, nullptr, QA, KB, Vf,
        3 * EMBED, 0, 0, 0, 0, 1.0f);

    // V transpose + split
    vtrans_kernel<<<dim3(SEQ / 32, EMBED / 32, BATCH), dim3(32, 8)>>>(Vf, VB);

    // GEMM2: scores = Q @ K^T / 32   (per batch M=N=2048, Keff=3072)
    mma_gemm<0><<<dim3(SEQ / 128, SEQ / 128, BATCH), 256, SMEM_B>>>(
        QA, KB, nullptr, sc, nullptr, nullptr, nullptr,
        3 * EMBED, SEQ,
        (long long)SEQ * 3 * EMBED, (long long)SEQ * 3 * EMBED, (long long)SEQ * SEQ,
        0.03125f);

    // softmax + split -> PA
    softmax_pa_kernel<<<BATCH * SEQ, 256>>>(sc, PA);

    // GEMM3: out = P @ V   (per batch M=2048, N=1024, Keff=6144)
    mma_gemm<0><<<dim3(EMBED / 128, SEQ / 128, BATCH), 256, SMEM_B>>>(
        PA, VB, nullptr, out, nullptr, nullptr, nullptr,
        3 * SEQ, EMBED,
        (long long)SEQ * 3 * SEQ, (long long)EMBED * 3 * SEQ, (long long)SEQ * EMBED,
        1.0f);
}

// round 7
// speedup vs baseline: 1.2414x; 1.1089x over previous
#include <cuda_runtime.h>
#include <cuda_bf16.h>
#include <cuda_fp16.h>
#include <math.h>
#include <stdint.h>

#define BATCH   8
#define SEQ     2048
#define EMBED   1024
#define QKVD    3072

// ---------------- scratch (device globals; no allocs allowed) ---------------
__device__ float         g_V     [(size_t)BATCH * SEQ * EMBED];   // fp32 V
__device__ float         g_scores[(size_t)BATCH * SEQ * SEQ];
__device__ __nv_bfloat16 g_A1[(size_t)BATCH * SEQ * (3*EMBED)];   // x split  (A-order, bf16 3-term)
__device__ __nv_bfloat16 g_B1[(size_t)QKVD * (3*EMBED)];          // W split  (B-order, bf16 3-term)
__device__ __nv_bfloat16 g_QA[(size_t)BATCH * SEQ * (3*EMBED)];   // Q split  (A-order)
__device__ __nv_bfloat16 g_KB[(size_t)BATCH * SEQ * (3*EMBED)];   // K split  (B-order)
__device__ __half        g_VB[(size_t)BATCH * EMBED * (2*SEQ)];   // V^T fp16 [hi|hi]
__device__ __half        g_PA[(size_t)BATCH * SEQ * (2*SEQ)];     // probs fp16 [hi|lo]

// ---------------- asm helpers ------------------------------------------------
__device__ __forceinline__ uint32_t smem_u32(const void* p) {
    uint32_t a;
    asm("{ .reg .u64 t; cvta.to.shared.u64 t, %1; cvt.u32.u64 %0, t; }" : "=r"(a) : "l"(p));
    return a;
}
#define CP_ASYNC16(dst, src) \
    asm volatile("cp.async.cg.shared.global [%0], [%1], 16;" :: "r"(dst), "l"(src))
#define CP_COMMIT() asm volatile("cp.async.commit_group;" ::: "memory")
#define CP_WAIT1()  asm volatile("cp.async.wait_group 1;"  ::: "memory")
#define LDMX4(r, addr) \
    asm volatile("ldmatrix.sync.aligned.m8n8.x4.shared.b16 {%0,%1,%2,%3}, [%4];" \
        : "=r"((r)[0]), "=r"((r)[1]), "=r"((r)[2]), "=r"((r)[3]) : "r"(addr))
#define MMA16816_BF16(d, a, b) \
    asm volatile("mma.sync.aligned.m16n8k16.row.col.f32.bf16.bf16.f32 " \
        "{%0,%1,%2,%3}, {%4,%5,%6,%7}, {%8,%9}, {%0,%1,%2,%3};" \
        : "+f"((d)[0]), "+f"((d)[1]), "+f"((d)[2]), "+f"((d)[3]) \
        : "r"((a)[0]), "r"((a)[1]), "r"((a)[2]), "r"((a)[3]), "r"((b)[0]), "r"((b)[1]))
#define MMA16816_F16(d, a, b) \
    asm volatile("mma.sync.aligned.m16n8k16.row.col.f32.f16.f16.f32 " \
        "{%0,%1,%2,%3}, {%4,%5,%6,%7}, {%8,%9}, {%0,%1,%2,%3};" \
        : "+f"((d)[0]), "+f"((d)[1]), "+f"((d)[2]), "+f"((d)[3]) \
        : "r"((a)[0]), "r"((a)[1]), "r"((a)[2]), "r"((a)[3]), "r"((b)[0]), "r"((b)[1]))

// ---------------- tensor-core GEMM -------------------------------------------
// C[m,n] = alpha * sum_k A[m,k] B[n,k]   (A, B row-major 16-bit, K-major)
// CTA tile 128x128, K-chunk 64, 3-stage cp.async, single-sync multistage loop.
// 256 threads = 8 warps (2m x 4n), warp tile 64x32, mma.m16n8k16 -> fp32.
// MODE 0: plain epilogue (alpha scale) -> fp32 C
// MODE 1: fused qkv epilogue (bias + per-region split to QA/KB/Vf)
// F16:    operands are fp16 instead of bf16 (MMA opcode only difference)
#define LDT     72                       // smem row pitch in halves (144 B)
#define ATILE_H (128 * LDT)
#define STAGE_H (2 * ATILE_H)            // A+B tile per stage (halves)
#define NSTAGE  3
#define SMEM_B  (NSTAGE * STAGE_H * 2)   // 110592 bytes

__device__ __forceinline__ void load_chunk(uint32_t sb, int stage,
    const __nv_bfloat16* __restrict__ Ag, const __nv_bfloat16* __restrict__ Bg,
    int K, int k0, int tid)
{
    const int r = tid >> 1;
    const int c = (tid & 1) * 32;
    const uint32_t base = sb + (uint32_t)stage * (STAGE_H * 2) + (r * LDT + c) * 2;
    const __nv_bfloat16* as = Ag + (size_t)r * K + k0 + c;
    const __nv_bfloat16* bs = Bg + (size_t)r * K + k0 + c;
    #pragma unroll
    for (int i = 0; i < 4; ++i) CP_ASYNC16(base + i * 16, as + i * 8);
    #pragma unroll
    for (int i = 0; i < 4; ++i) CP_ASYNC16(base + ATILE_H * 2 + i * 16, bs + i * 8);
}

template<int MODE, bool F16>
__global__ void __launch_bounds__(256, 2) mma_gemm(
    const __nv_bfloat16* __restrict__ A, const __nv_bfloat16* __restrict__ B,
    const float* __restrict__ bias, float* __restrict__ C,
    __nv_bfloat16* __restrict__ QA, __nv_bfloat16* __restrict__ KB,
    float* __restrict__ Vf,
    int K, int ldc, long long sA, long long sB, long long sC, float alpha)
{
    extern __shared__ char smem[];
    const uint32_t sb = smem_u32(smem);
    const int tid = threadIdx.x;
    const int lane = tid & 31;
    const int wid = tid >> 5;
    const int wm = (wid & 1) * 64;
    const int wn = (wid >> 1) * 32;

    const __nv_bfloat16* Ag = A + blockIdx.z * sA + (size_t)(blockIdx.y * 128) * K;
    const __nv_bfloat16* Bg = B + blockIdx.z * sB + (size_t)(blockIdx.x * 128) * K;

    const int ar = (lane & 7) + ((lane >> 3) & 1) * 8;
    const int ak = (lane >> 4) * 8;
    const int bn = (lane & 7) + ((lane >> 4) & 1) * 8;
    const int bk = ((lane >> 3) & 1) * 8;

    float acc[4][4][4];
    #pragma unroll
    for (int i = 0; i < 4; ++i)
        #pragma unroll
        for (int j = 0; j < 4; ++j)
            #pragma unroll
            for (int q = 0; q < 4; ++q) acc[i][j][q] = 0.0f;

    const int nch = K / 64;
    load_chunk(sb, 0, Ag, Bg, K, 0, tid);  CP_COMMIT();
    load_chunk(sb, 1, Ag, Bg, K, 64, tid); CP_COMMIT();

    for (int ch = 0; ch < nch; ++ch) {
        const int stage = ch % NSTAGE;
        CP_WAIT1();              // chunk ch resident
        __syncthreads();         // publish cp.async writes; free stage (ch-1)%3

        if (ch + 2 < nch) load_chunk(sb, (ch + 2) % NSTAGE, Ag, Bg, K, (ch + 2) * 64, tid);
        CP_COMMIT();

        const uint32_t abase = sb + (uint32_t)stage * (STAGE_H * 2);
        const uint32_t bbase = abase + ATILE_H * 2;
        #pragma unroll
        for (int s = 0; s < 4; ++s) {
            uint32_t a[4][4];
            #pragma unroll
            for (int mf = 0; mf < 4; ++mf)
                LDMX4(a[mf], abase + ((wm + mf * 16 + ar) * LDT + s * 16 + ak) * 2);
            uint32_t b[2][4];
            #pragma unroll
            for (int n2 = 0; n2 < 2; ++n2)
                LDMX4(b[n2], bbase + ((wn + n2 * 16 + bn) * LDT + s * 16 + bk) * 2);
            #pragma unroll
            for (int mf = 0; mf < 4; ++mf)
                #pragma unroll
                for (int nf = 0; nf < 4; ++nf) {
                    if constexpr (F16) {
                        MMA16816_F16(acc[mf][nf], a[mf], &b[nf >> 1][(nf & 1) * 2]);
                    } else {
                        MMA16816_BF16(acc[mf][nf], a[mf], &b[nf >> 1][(nf & 1) * 2]);
                    }
                }
        }
    }

    // ---------------- epilogue ----------------
    const int g  = lane >> 2;
    const int tg = lane & 3;

    if (MODE == 0) {
        float* Cg = C + blockIdx.z * sC;
        #pragma unroll
        for (int mf = 0; mf < 4; ++mf) {
            const int row0 = blockIdx.y * 128 + wm + mf * 16 + g;
            #pragma unroll
            for (int nf = 0; nf < 4; ++nf) {
                const int col = blockIdx.x * 128 + wn + nf * 8 + tg * 2;
                float2 v0 = make_float2(acc[mf][nf][0] * alpha, acc[mf][nf][1] * alpha);
                float2 v1 = make_float2(acc[mf][nf][2] * alpha, acc[mf][nf][3] * alpha);
                *reinterpret_cast<float2*>(Cg + (size_t)row0 * ldc + col) = v0;
                *reinterpret_cast<float2*>(Cg + (size_t)(row0 + 8) * ldc + col) = v1;
            }
        }
    } else {
        const int cblk = blockIdx.x * 128;
        const int region = cblk >> 10;               // 0=Q 1=K 2=V
        #pragma unroll
        for (int mf = 0; mf < 4; ++mf) {
            const int row0 = blockIdx.y * 128 + wm + mf * 16 + g;
            #pragma unroll
            for (int nf = 0; nf < 4; ++nf) {
                const int gcol = cblk + wn + nf * 8 + tg * 2;
                const float2 bb = *reinterpret_cast<const float2*>(bias + gcol);
                float v[2][2];
                v[0][0] = acc[mf][nf][0] + bb.x;  v[0][1] = acc[mf][nf][1] + bb.y;
                v[1][0] = acc[mf][nf][2] + bb.x;  v[1][1] = acc[mf][nf][3] + bb.y;
                const int lcol = gcol & 1023;
                if (region == 2) {
                    *reinterpret_cast<float2*>(Vf + (size_t)row0 * EMBED + lcol)
                        = make_float2(v[0][0], v[0][1]);
                    *reinterpret_cast<float2*>(Vf + (size_t)(row0 + 8) * EMBED + lcol)
                        = make_float2(v[1][0], v[1][1]);
                } else {
                    __nv_bfloat16* dst = (region == 0) ? QA : KB;
                    #pragma unroll
                    for (int h = 0; h < 2; ++h) {
                        const int r = row0 + h * 8;
                        __nv_bfloat16 hi0 = __float2bfloat16(v[h][0]);
                        __nv_bfloat16 hi1 = __float2bfloat16(v[h][1]);
                        __nv_bfloat16 lo0 = __float2bfloat16(v[h][0] - __bfloat162float(hi0));
                        __nv_bfloat16 lo1 = __float2bfloat16(v[h][1] - __bfloat162float(hi1));
                        __nv_bfloat162 hp(hi0, hi1), lp(lo0, lo1);
                        __nv_bfloat16* d0 = dst + (size_t)r * (3 * EMBED) + lcol;
                        if (region == 0) {   // QA: hi | lo | hi
                            *reinterpret_cast<__nv_bfloat162*>(d0)             = hp;
                            *reinterpret_cast<__nv_bfloat162*>(d0 + EMBED)     = lp;
                            *reinterpret_cast<__nv_bfloat162*>(d0 + 2 * EMBED) = hp;
                        } else {             // KB: hi | hi | lo
                            *reinterpret_cast<__nv_bfloat162*>(d0)             = hp;
                            *reinterpret_cast<__nv_bfloat162*>(d0 + EMBED)     = hp;
                            *reinterpret_cast<__nv_bfloat162*>(d0 + 2 * EMBED) = lp;
                        }
                    }
                }
            }
        }
    }
}

// ---------------- fp32 -> bf16 hi/lo split (for x and W inputs) --------------
template<bool AORDER>
__global__ void split_kernel(const float* __restrict__ src, __nv_bfloat16* __restrict__ dst,
                             int K, int srcPitch, int srcOff, long long nvec)
{
    long long i = blockIdx.x * (long long)blockDim.x + threadIdx.x;
    if (i >= nvec) return;
    long long e = i * 4;
    int row = (int)(e / K), col = (int)(e % K);
    const float4 v = *reinterpret_cast<const float4*>(src + (size_t)row * srcPitch + srcOff + col);
    float vs[4] = { v.x, v.y, v.z, v.w };
    __nv_bfloat16 h[4], l[4];
    #pragma unroll
    for (int j = 0; j < 4; ++j) {
        h[j] = __float2bfloat16(vs[j]);
        l[j] = __float2bfloat16(vs[j] - __bfloat162float(h[j]));
    }
    __nv_bfloat162 hp0(h[0], h[1]), hp1(h[2], h[3]);
    __nv_bfloat162 lp0(l[0], l[1]), lp1(l[2], l[3]);
    __nv_bfloat16* d0 = dst + (size_t)row * 3 * K + col;
    reinterpret_cast<__nv_bfloat162*>(d0)[0] = hp0;
    reinterpret_cast<__nv_bfloat162*>(d0)[1] = hp1;
    if (AORDER) {
        reinterpret_cast<__nv_bfloat162*>(d0 + K)[0] = lp0;
        reinterpret_cast<__nv_bfloat162*>(d0 + K)[1] = lp1;
        reinterpret_cast<__nv_bfloat162*>(d0 + 2 * K)[0] = hp0;
        reinterpret_cast<__nv_bfloat162*>(d0 + 2 * K)[1] = hp1;
    } else {
        reinterpret_cast<__nv_bfloat162*>(d0 + K)[0] = hp0;
        reinterpret_cast<__nv_bfloat162*>(d0 + K)[1] = hp1;
        reinterpret_cast<__nv_bfloat162*>(d0 + 2 * K)[0] = lp0;
        reinterpret_cast<__nv_bfloat162*>(d0 + 2 * K)[1] = lp1;
    }
}

// ---------------- V transpose -> fp16 [hi|hi] (B-order, 2-term) --------------
__global__ void vtrans_kernel(const float* __restrict__ Vf, __half* __restrict__ VB)
{
    __shared__ float t[32][33];
    const int b = blockIdx.z;
    const int n0 = blockIdx.x * 32, e0 = blockIdx.y * 32;
    const int tx = threadIdx.x, ty = threadIdx.y;
    const float* src = Vf + (size_t)b * SEQ * EMBED;
    #pragma unroll
    for (int i = 0; i < 4; ++i)
        t[ty + 8 * i][tx] = src[(size_t)(n0 + ty + 8 * i) * EMBED + e0 + tx];
    __syncthreads();
    __half* dst = VB + (size_t)b * EMBED * (2 * SEQ);
    #pragma unroll
    for (int i = 0; i < 4; ++i) {
        const __half h = __float2half(t[tx][ty + 8 * i]);
        const size_t base = (size_t)(e0 + ty + 8 * i) * (2 * SEQ) + n0 + tx;
        dst[base]       = h;
        dst[base + SEQ] = h;
    }
}

// ---------------- softmax + prob split to fp16 (A-order [hi|lo]) -------------
__global__ void softmax_pa_kernel(const float* __restrict__ s, __half* __restrict__ PA)
{
    __shared__ float row[SEQ];
    __shared__ float red[8];
    const int tid = threadIdx.x;
    const float4* p4 = reinterpret_cast<const float4*>(s + (size_t)blockIdx.x * SEQ);
    float4* r4 = reinterpret_cast<float4*>(row);

    float lmax = -3.4e38f;
    #pragma unroll
    for (int it = 0; it < 2; ++it) {
        const float4 t = p4[tid + it * 256];
        r4[tid + it * 256] = t;
        lmax = fmaxf(lmax, fmaxf(fmaxf(t.x, t.y), fmaxf(t.z, t.w)));
    }
    #pragma unroll
    for (int o = 16; o; o >>= 1) lmax = fmaxf(lmax, __shfl_xor_sync(0xffffffffu, lmax, o));
    if ((tid & 31) == 0) red[tid >> 5] = lmax;
    __syncthreads();
    const float rmax = fmaxf(fmaxf(fmaxf(red[0], red[1]), fmaxf(red[2], red[3])),
                             fmaxf(fmaxf(red[4], red[5]), fmaxf(red[6], red[7])));
    __syncthreads();

    float lsum = 0.0f;
    #pragma unroll
    for (int it = 0; it < 2; ++it) {
        float4 t = r4[tid + it * 256];
        t.x = expf(t.x - rmax); t.y = expf(t.y - rmax);
        t.z = expf(t.z - rmax); t.w = expf(t.w - rmax);
        r4[tid + it * 256] = t;
        lsum += (t.x + t.y) + (t.z + t.w);
    }
    #pragma unroll
    for (int o = 16; o; o >>= 1) lsum += __shfl_xor_sync(0xffffffffu, lsum, o);
    if ((tid & 31) == 0) red[tid >> 5] = lsum;
    __syncthreads();
    const float inv = 1.0f / (((red[0] + red[1]) + (red[2] + red[3])) +
                              ((red[4] + red[5]) + (red[6] + red[7])));

    __half* pa = PA + (size_t)blockIdx.x * (2 * SEQ);
    #pragma unroll
    for (int it = 0; it < 2; ++it) {
        float4 t = r4[tid + it * 256];
        t.x *= inv; t.y *= inv; t.z *= inv; t.w *= inv;
        float vs[4] = { t.x, t.y, t.z, t.w };
        __half h[4], l[4];
        #pragma unroll
        for (int j = 0; j < 4; ++j) {
            h[j] = __float2half(vs[j]);
            l[j] = __float2half(vs[j] - __half2float(h[j]));
        }
        const int idx = (tid + it * 256) * 4;
        __half2 hp0(h[0], h[1]), hp1(h[2], h[3]);
        __half2 lp0(l[0], l[1]), lp1(l[2], l[3]);
        reinterpret_cast<__half2*>(pa + idx)[0] = hp0;
        reinterpret_cast<__half2*>(pa + idx)[1] = hp1;
        reinterpret_cast<__half2*>(pa + SEQ + idx)[0] = lp0;
        reinterpret_cast<__half2*>(pa + SEQ + idx)[1] = lp1;
    }
}

// -----------------------------------------------------------------------------
extern "C" void kernel_launch(void* const* d_in, const int* in_sizes, int n_in,
                              void* d_out, int out_size)
{
    const float* x = (const float*)d_in[0];
    const float* W = (const float*)d_in[1];
    const float* b = (const float*)d_in[2];
    float* out = (float*)d_out;

    float *Vf, *sc;
    __nv_bfloat16 *A1, *B1, *QA, *KB;
    __half *VB, *PA;
    { void* p; cudaGetSymbolAddress(&p, g_V);      Vf = (float*)p; }
    { void* p; cudaGetSymbolAddress(&p, g_scores); sc = (float*)p; }
    { void* p; cudaGetSymbolAddress(&p, g_A1); A1 = (__nv_bfloat16*)p; }
    { void* p; cudaGetSymbolAddress(&p, g_B1); B1 = (__nv_bfloat16*)p; }
    { void* p; cudaGetSymbolAddress(&p, g_QA); QA = (__nv_bfloat16*)p; }
    { void* p; cudaGetSymbolAddress(&p, g_KB); KB = (__nv_bfloat16*)p; }
    { void* p; cudaGetSymbolAddress(&p, g_VB); VB = (__half*)p; }
    { void* p; cudaGetSymbolAddress(&p, g_PA); PA = (__half*)p; }

    cudaFuncSetAttribute(mma_gemm<0,false>, cudaFuncAttributeMaxDynamicSharedMemorySize, SMEM_B);
    cudaFuncSetAttribute(mma_gemm<1,false>, cudaFuncAttributeMaxDynamicSharedMemorySize, SMEM_B);
    cudaFuncSetAttribute(mma_gemm<0,true >, cudaFuncAttributeMaxDynamicSharedMemorySize, SMEM_B);

    const long long MN = (long long)BATCH * SEQ;   // 16384

    // input splits: x -> A1 (A-order), W -> B1 (B-order)
    split_kernel<true ><<<(unsigned)((MN * EMBED / 4 + 255) / 256), 256>>>(
        x, A1, EMBED, EMBED, 0, MN * EMBED / 4);
    split_kernel<false><<<(unsigned)(((long long)QKVD * EMBED / 4 + 255) / 256), 256>>>(
        W, B1, EMBED, EMBED, 0, (long long)QKVD * EMBED / 4);

    // GEMM1 (fused): qkv = x @ W^T + b, epilogue emits QA / KB / Vf directly
    mma_gemm<1,false><<<dim3(QKVD / 128, (unsigned)(MN / 128), 1), 256, SMEM_B>>>(
        A1, B1, b, nullptr, QA, KB, Vf,
        3 * EMBED, 0, 0, 0, 0, 1.0f);

    // V transpose -> fp16 [hi|hi]
    vtrans_kernel<<<dim3(SEQ / 32, EMBED / 32, BATCH), dim3(32, 8)>>>(Vf, VB);

    // GEMM2: scores = Q @ K^T / 32   (per batch M=N=2048, Keff=3072, bf16 3-term)
    mma_gemm<0,false><<<dim3(SEQ / 128, SEQ / 128, BATCH), 256, SMEM_B>>>(
        QA, KB, nullptr, sc, nullptr, nullptr, nullptr,
        3 * EMBED, SEQ,
        (long long)SEQ * 3 * EMBED, (long long)SEQ * 3 * EMBED, (long long)SEQ * SEQ,
        0.03125f);

    // softmax + fp16 [hi|lo] split -> PA
    softmax_pa_kernel<<<BATCH * SEQ, 256>>>(sc, PA);

    // GEMM3: out = P @ V   (per batch M=2048, N=1024, Keff=4096, fp16 2-term)
    mma_gemm<0,true><<<dim3(EMBED / 128, SEQ / 128, BATCH), 256, SMEM_B>>>(
        reinterpret_cast<const __nv_bfloat16*>(PA),
        reinterpret_cast<const __nv_bfloat16*>(VB),
        nullptr, out, nullptr, nullptr, nullptr,
        2 * SEQ, EMBED,
        (long long)SEQ * 2 * SEQ, (long long)EMBED * 2 * SEQ, (long long)SEQ * EMBED,
        1.0f);
}

// round 8
// speedup vs baseline: 1.4005x; 1.1282x over previous
#include <cuda_runtime.h>
#include <cuda_bf16.h>
#include <cuda_fp16.h>
#include <math.h>
#include <stdint.h>

#define BATCH   8
#define SEQ     2048
#define EMBED   1024
#define QKVD    3072

// ---------------- scratch (device globals; no allocs allowed) ---------------
__device__ __half        g_Vh    [(size_t)BATCH * SEQ * EMBED];   // fp16 V (row-major)
__device__ float         g_scores[(size_t)BATCH * SEQ * SEQ];
__device__ __nv_bfloat16 g_A1[(size_t)BATCH * SEQ * (3*EMBED)];   // x split  (A-order bf16 3-term)
__device__ __nv_bfloat16 g_B1[(size_t)QKVD * (3*EMBED)];          // W split  (B-order bf16 3-term)
__device__ __half        g_QA[(size_t)BATCH * SEQ * (2*EMBED)];   // Q fp16 [hi|lo]
__device__ __half        g_KB[(size_t)BATCH * SEQ * (2*EMBED)];   // K fp16 [hi|hi]
__device__ __half        g_VB[(size_t)BATCH * EMBED * (2*SEQ)];   // V^T fp16 [hi|hi]
__device__ __half        g_PA[(size_t)BATCH * SEQ * (2*SEQ)];     // probs fp16 [hi|lo]

// ---------------- asm helpers ------------------------------------------------
__device__ __forceinline__ uint32_t smem_u32(const void* p) {
    uint32_t a;
    asm("{ .reg .u64 t; cvta.to.shared.u64 t, %1; cvt.u32.u64 %0, t; }" : "=r"(a) : "l"(p));
    return a;
}
#define CP_ASYNC16(dst, src) \
    asm volatile("cp.async.cg.shared.global [%0], [%1], 16;" :: "r"(dst), "l"(src))
#define CP_COMMIT() asm volatile("cp.async.commit_group;" ::: "memory")
#define CP_WAIT1()  asm volatile("cp.async.wait_group 1;"  ::: "memory")
#define LDMX4(r, addr) \
    asm volatile("ldmatrix.sync.aligned.m8n8.x4.shared.b16 {%0,%1,%2,%3}, [%4];" \
        : "=r"((r)[0]), "=r"((r)[1]), "=r"((r)[2]), "=r"((r)[3]) : "r"(addr))
#define MMA16816_BF16(d, a, b) \
    asm volatile("mma.sync.aligned.m16n8k16.row.col.f32.bf16.bf16.f32 " \
        "{%0,%1,%2,%3}, {%4,%5,%6,%7}, {%8,%9}, {%0,%1,%2,%3};" \
        : "+f"((d)[0]), "+f"((d)[1]), "+f"((d)[2]), "+f"((d)[3]) \
        : "r"((a)[0]), "r"((a)[1]), "r"((a)[2]), "r"((a)[3]), "r"((b)[0]), "r"((b)[1]))
#define MMA16816_F16(d, a, b) \
    asm volatile("mma.sync.aligned.m16n8k16.row.col.f32.f16.f16.f32 " \
        "{%0,%1,%2,%3}, {%4,%5,%6,%7}, {%8,%9}, {%0,%1,%2,%3};" \
        : "+f"((d)[0]), "+f"((d)[1]), "+f"((d)[2]), "+f"((d)[3]) \
        : "r"((a)[0]), "r"((a)[1]), "r"((a)[2]), "r"((a)[3]), "r"((b)[0]), "r"((b)[1]))

// ---------------- tensor-core GEMM -------------------------------------------
// C[m,n] = alpha * sum_k A[m,k] B[n,k]   (A, B row-major 16-bit, K-major)
// CTA tile 128x128, K-chunk 64, 3-stage cp.async, single-sync multistage loop.
// 256 threads = 8 warps (2m x 4n), warp tile 64x32, mma.m16n8k16 -> fp32.
// MODE 0: plain epilogue (alpha scale) -> fp32 C
// MODE 1: fused qkv epilogue (bias + per-region split to QA/KB/Vh, fp16)
// F16:    operands are fp16 instead of bf16 (MMA opcode only difference)
#define LDT     72                       // smem row pitch in halves (144 B)
#define ATILE_H (128 * LDT)
#define STAGE_H (2 * ATILE_H)            // A+B tile per stage (halves)
#define NSTAGE  3
#define SMEM_B  (NSTAGE * STAGE_H * 2)   // 110592 bytes

__device__ __forceinline__ void load_chunk(uint32_t sb, int stage,
    const __nv_bfloat16* __restrict__ Ag, const __nv_bfloat16* __restrict__ Bg,
    int K, int k0, int tid)
{
    const int r = tid >> 1;
    const int c = (tid & 1) * 32;
    const uint32_t base = sb + (uint32_t)stage * (STAGE_H * 2) + (r * LDT + c) * 2;
    const __nv_bfloat16* as = Ag + (size_t)r * K + k0 + c;
    const __nv_bfloat16* bs = Bg + (size_t)r * K + k0 + c;
    #pragma unroll
    for (int i = 0; i < 4; ++i) CP_ASYNC16(base + i * 16, as + i * 8);
    #pragma unroll
    for (int i = 0; i < 4; ++i) CP_ASYNC16(base + ATILE_H * 2 + i * 16, bs + i * 8);
}

template<int MODE, bool F16>
__global__ void __launch_bounds__(256, 2) mma_gemm(
    const __nv_bfloat16* __restrict__ A, const __nv_bfloat16* __restrict__ B,
    const float* __restrict__ bias, float* __restrict__ C,
    __half* __restrict__ QA, __half* __restrict__ KB, __half* __restrict__ Vh,
    int K, int ldc, long long sA, long long sB, long long sC, float alpha)
{
    extern __shared__ char smem[];
    const uint32_t sb = smem_u32(smem);
    const int tid = threadIdx.x;
    const int lane = tid & 31;
    const int wid = tid >> 5;
    const int wm = (wid & 1) * 64;
    const int wn = (wid >> 1) * 32;

    const __nv_bfloat16* Ag = A + blockIdx.z * sA + (size_t)(blockIdx.y * 128) * K;
    const __nv_bfloat16* Bg = B + blockIdx.z * sB + (size_t)(blockIdx.x * 128) * K;

    const int ar = (lane & 7) + ((lane >> 3) & 1) * 8;
    const int ak = (lane >> 4) * 8;
    const int bn = (lane & 7) + ((lane >> 4) & 1) * 8;
    const int bk = ((lane >> 3) & 1) * 8;

    float acc[4][4][4];
    #pragma unroll
    for (int i = 0; i < 4; ++i)
        #pragma unroll
        for (int j = 0; j < 4; ++j)
            #pragma unroll
            for (int q = 0; q < 4; ++q) acc[i][j][q] = 0.0f;

    const int nch = K / 64;
    load_chunk(sb, 0, Ag, Bg, K, 0, tid);  CP_COMMIT();
    load_chunk(sb, 1, Ag, Bg, K, 64, tid); CP_COMMIT();

    for (int ch = 0; ch < nch; ++ch) {
        const int stage = ch % NSTAGE;
        CP_WAIT1();              // chunk ch resident
        __syncthreads();         // publish cp.async writes; free stage (ch-1)%3

        if (ch + 2 < nch) load_chunk(sb, (ch + 2) % NSTAGE, Ag, Bg, K, (ch + 2) * 64, tid);
        CP_COMMIT();

        const uint32_t abase = sb + (uint32_t)stage * (STAGE_H * 2);
        const uint32_t bbase = abase + ATILE_H * 2;
        #pragma unroll
        for (int s = 0; s < 4; ++s) {
            uint32_t a[4][4];
            #pragma unroll
            for (int mf = 0; mf < 4; ++mf)
                LDMX4(a[mf], abase + ((wm + mf * 16 + ar) * LDT + s * 16 + ak) * 2);
            uint32_t b[2][4];
            #pragma unroll
            for (int n2 = 0; n2 < 2; ++n2)
                LDMX4(b[n2], bbase + ((wn + n2 * 16 + bn) * LDT + s * 16 + bk) * 2);
            #pragma unroll
            for (int mf = 0; mf < 4; ++mf)
                #pragma unroll
                for (int nf = 0; nf < 4; ++nf) {
                    if constexpr (F16) {
                        MMA16816_F16(acc[mf][nf], a[mf], &b[nf >> 1][(nf & 1) * 2]);
                    } else {
                        MMA16816_BF16(acc[mf][nf], a[mf], &b[nf >> 1][(nf & 1) * 2]);
                    }
                }
        }
    }

    // ---------------- epilogue ----------------
    const int g  = lane >> 2;
    const int tg = lane & 3;

    if (MODE == 0) {
        float* Cg = C + blockIdx.z * sC;
        #pragma unroll
        for (int mf = 0; mf < 4; ++mf) {
            const int row0 = blockIdx.y * 128 + wm + mf * 16 + g;
            #pragma unroll
            for (int nf = 0; nf < 4; ++nf) {
                const int col = blockIdx.x * 128 + wn + nf * 8 + tg * 2;
                float2 v0 = make_float2(acc[mf][nf][0] * alpha, acc[mf][nf][1] * alpha);
                float2 v1 = make_float2(acc[mf][nf][2] * alpha, acc[mf][nf][3] * alpha);
                *reinterpret_cast<float2*>(Cg + (size_t)row0 * ldc + col) = v0;
                *reinterpret_cast<float2*>(Cg + (size_t)(row0 + 8) * ldc + col) = v1;
            }
        }
    } else {
        const int cblk = blockIdx.x * 128;
        const int region = cblk >> 10;               // 0=Q 1=K 2=V
        #pragma unroll
        for (int mf = 0; mf < 4; ++mf) {
            const int row0 = blockIdx.y * 128 + wm + mf * 16 + g;
            #pragma unroll
            for (int nf = 0; nf < 4; ++nf) {
                const int gcol = cblk + wn + nf * 8 + tg * 2;
                const float2 bb = *reinterpret_cast<const float2*>(bias + gcol);
                float v[2][2];
                v[0][0] = acc[mf][nf][0] + bb.x;  v[0][1] = acc[mf][nf][1] + bb.y;
                v[1][0] = acc[mf][nf][2] + bb.x;  v[1][1] = acc[mf][nf][3] + bb.y;
                const int lcol = gcol & 1023;
                #pragma unroll
                for (int h = 0; h < 2; ++h) {
                    const int r = row0 + h * 8;
                    const __half hi0 = __float2half(v[h][0]);
                    const __half hi1 = __float2half(v[h][1]);
                    const __half2 hp(hi0, hi1);
                    if (region == 2) {               // V: single fp16
                        *reinterpret_cast<__half2*>(Vh + (size_t)r * EMBED + lcol) = hp;
                    } else if (region == 0) {        // QA: hi | lo (exact split)
                        const __half lo0 = __float2half(v[h][0] - __half2float(hi0));
                        const __half lo1 = __float2half(v[h][1] - __half2float(hi1));
                        __half* d0 = QA + (size_t)r * (2 * EMBED) + lcol;
                        *reinterpret_cast<__half2*>(d0)         = hp;
                        *reinterpret_cast<__half2*>(d0 + EMBED) = __half2(lo0, lo1);
                    } else {                         // KB: hi | hi
                        __half* d0 = KB + (size_t)r * (2 * EMBED) + lcol;
                        *reinterpret_cast<__half2*>(d0)         = hp;
                        *reinterpret_cast<__half2*>(d0 + EMBED) = hp;
                    }
                }
            }
        }
    }
}

// ---------------- fp32 -> bf16 hi/lo split (for x and W inputs) --------------
template<bool AORDER>
__global__ void split_kernel(const float* __restrict__ src, __nv_bfloat16* __restrict__ dst,
                             int K, int srcPitch, int srcOff, long long nvec)
{
    long long i = blockIdx.x * (long long)blockDim.x + threadIdx.x;
    if (i >= nvec) return;
    long long e = i * 4;
    int row = (int)(e / K), col = (int)(e % K);
    const float4 v = *reinterpret_cast<const float4*>(src + (size_t)row * srcPitch + srcOff + col);
    float vs[4] = { v.x, v.y, v.z, v.w };
    __nv_bfloat16 h[4], l[4];
    #pragma unroll
    for (int j = 0; j < 4; ++j) {
        h[j] = __float2bfloat16(vs[j]);
        l[j] = __float2bfloat16(vs[j] - __bfloat162float(h[j]));
    }
    __nv_bfloat162 hp0(h[0], h[1]), hp1(h[2], h[3]);
    __nv_bfloat162 lp0(l[0], l[1]), lp1(l[2], l[3]);
    __nv_bfloat16* d0 = dst + (size_t)row * 3 * K + col;
    reinterpret_cast<__nv_bfloat162*>(d0)[0] = hp0;
    reinterpret_cast<__nv_bfloat162*>(d0)[1] = hp1;
    if (AORDER) {
        reinterpret_cast<__nv_bfloat162*>(d0 + K)[0] = lp0;
        reinterpret_cast<__nv_bfloat162*>(d0 + K)[1] = lp1;
        reinterpret_cast<__nv_bfloat162*>(d0 + 2 * K)[0] = hp0;
        reinterpret_cast<__nv_bfloat162*>(d0 + 2 * K)[1] = hp1;
    } else {
        reinterpret_cast<__nv_bfloat162*>(d0 + K)[0] = hp0;
        reinterpret_cast<__nv_bfloat162*>(d0 + K)[1] = hp1;
        reinterpret_cast<__nv_bfloat162*>(d0 + 2 * K)[0] = lp0;
        reinterpret_cast<__nv_bfloat162*>(d0 + 2 * K)[1] = lp1;
    }
}

// ---------------- V transpose fp16 -> fp16 [hi|hi] (B-order) -----------------
__global__ void vtrans_kernel(const __half* __restrict__ Vh, __half* __restrict__ VB)
{
    __shared__ __half t[32][34];
    const int b = blockIdx.z;
    const int n0 = blockIdx.x * 32, e0 = blockIdx.y * 32;
    const int tx = threadIdx.x, ty = threadIdx.y;
    const __half* src = Vh + (size_t)b * SEQ * EMBED;
    #pragma unroll
    for (int i = 0; i < 4; ++i)
        t[ty + 8 * i][tx] = src[(size_t)(n0 + ty + 8 * i) * EMBED + e0 + tx];
    __syncthreads();
    __half* dst = VB + (size_t)b * EMBED * (2 * SEQ);
    #pragma unroll
    for (int i = 0; i < 4; ++i) {
        const __half h = t[tx][ty + 8 * i];
        const size_t base = (size_t)(e0 + ty + 8 * i) * (2 * SEQ) + n0 + tx;
        dst[base]       = h;
        dst[base + SEQ] = h;
    }
}

// ---------------- softmax + prob split to fp16 (A-order [hi|lo]) -------------
__global__ void softmax_pa_kernel(const float* __restrict__ s, __half* __restrict__ PA)
{
    __shared__ float row[SEQ];
    __shared__ float red[8];
    const int tid = threadIdx.x;
    const float4* p4 = reinterpret_cast<const float4*>(s + (size_t)blockIdx.x * SEQ);
    float4* r4 = reinterpret_cast<float4*>(row);

    float lmax = -3.4e38f;
    #pragma unroll
    for (int it = 0; it < 2; ++it) {
        const float4 t = p4[tid + it * 256];
        r4[tid + it * 256] = t;
        lmax = fmaxf(lmax, fmaxf(fmaxf(t.x, t.y), fmaxf(t.z, t.w)));
    }
    #pragma unroll
    for (int o = 16; o; o >>= 1) lmax = fmaxf(lmax, __shfl_xor_sync(0xffffffffu, lmax, o));
    if ((tid & 31) == 0) red[tid >> 5] = lmax;
    __syncthreads();
    const float rmax = fmaxf(fmaxf(fmaxf(red[0], red[1]), fmaxf(red[2], red[3])),
                             fmaxf(fmaxf(red[4], red[5]), fmaxf(red[6], red[7])));
    __syncthreads();

    float lsum = 0.0f;
    #pragma unroll
    for (int it = 0; it < 2; ++it) {
        float4 t = r4[tid + it * 256];
        t.x = expf(t.x - rmax); t.y = expf(t.y - rmax);
        t.z = expf(t.z - rmax); t.w = expf(t.w - rmax);
        r4[tid + it * 256] = t;
        lsum += (t.x + t.y) + (t.z + t.w);
    }
    #pragma unroll
    for (int o = 16; o; o >>= 1) lsum += __shfl_xor_sync(0xffffffffu, lsum, o);
    if ((tid & 31) == 0) red[tid >> 5] = lsum;
    __syncthreads();
    const float inv = 1.0f / (((red[0] + red[1]) + (red[2] + red[3])) +
                              ((red[4] + red[5]) + (red[6] + red[7])));

    __half* pa = PA + (size_t)blockIdx.x * (2 * SEQ);
    #pragma unroll
    for (int it = 0; it < 2; ++it) {
        float4 t = r4[tid + it * 256];
        t.x *= inv; t.y *= inv; t.z *= inv; t.w *= inv;
        float vs[4] = { t.x, t.y, t.z, t.w };
        __half h[4], l[4];
        #pragma unroll
        for (int j = 0; j < 4; ++j) {
            h[j] = __float2half(vs[j]);
            l[j] = __float2half(vs[j] - __half2float(h[j]));
        }
        const int idx = (tid + it * 256) * 4;
        __half2 hp0(h[0], h[1]), hp1(h[2], h[3]);
        __half2 lp0(l[0], l[1]), lp1(l[2], l[3]);
        reinterpret_cast<__half2*>(pa + idx)[0] = hp0;
        reinterpret_cast<__half2*>(pa + idx)[1] = hp1;
        reinterpret_cast<__half2*>(pa + SEQ + idx)[0] = lp0;
        reinterpret_cast<__half2*>(pa + SEQ + idx)[1] = lp1;
    }
}

// -----------------------------------------------------------------------------
extern "C" void kernel_launch(void* const* d_in, const int* in_sizes, int n_in,
                              void* d_out, int out_size)
{
    const float* x = (const float*)d_in[0];
    const float* W = (const float*)d_in[1];
    const float* b = (const float*)d_in[2];
    float* out = (float*)d_out;

    float *sc;
    __nv_bfloat16 *A1, *B1;
    __half *Vh, *QA, *KB, *VB, *PA;
    { void* p; cudaGetSymbolAddress(&p, g_Vh);     Vh = (__half*)p; }
    { void* p; cudaGetSymbolAddress(&p, g_scores); sc = (float*)p; }
    { void* p; cudaGetSymbolAddress(&p, g_A1); A1 = (__nv_bfloat16*)p; }
    { void* p; cudaGetSymbolAddress(&p, g_B1); B1 = (__nv_bfloat16*)p; }
    { void* p; cudaGetSymbolAddress(&p, g_QA); QA = (__half*)p; }
    { void* p; cudaGetSymbolAddress(&p, g_KB); KB = (__half*)p; }
    { void* p; cudaGetSymbolAddress(&p, g_VB); VB = (__half*)p; }
    { void* p; cudaGetSymbolAddress(&p, g_PA); PA = (__half*)p; }

    cudaFuncSetAttribute(mma_gemm<0,false>, cudaFuncAttributeMaxDynamicSharedMemorySize, SMEM_B);
    cudaFuncSetAttribute(mma_gemm<1,false>, cudaFuncAttributeMaxDynamicSharedMemorySize, SMEM_B);
    cudaFuncSetAttribute(mma_gemm<0,true >, cudaFuncAttributeMaxDynamicSharedMemorySize, SMEM_B);

    const long long MN = (long long)BATCH * SEQ;   // 16384

    // input splits: x -> A1 (A-order), W -> B1 (B-order)  [bf16 3-term]
    split_kernel<true ><<<(unsigned)((MN * EMBED / 4 + 255) / 256), 256>>>(
        x, A1, EMBED, EMBED, 0, MN * EMBED / 4);
    split_kernel<false><<<(unsigned)(((long long)QKVD * EMBED / 4 + 255) / 256), 256>>>(
        W, B1, EMBED, EMBED, 0, (long long)QKVD * EMBED / 4);

    // GEMM1 (fused): qkv = x @ W^T + b -> QA fp16[hi|lo], KB fp16[hi|hi], Vh fp16
    mma_gemm<1,false><<<dim3(QKVD / 128, (unsigned)(MN / 128), 1), 256, SMEM_B>>>(
        A1, B1, b, nullptr, QA, KB, Vh,
        3 * EMBED, 0, 0, 0, 0, 1.0f);

    // V transpose -> fp16 [hi|hi]
    vtrans_kernel<<<dim3(SEQ / 32, EMBED / 32, BATCH), dim3(32, 8)>>>(Vh, VB);

    // GEMM2: scores = Q @ K^T / 32   (per batch M=N=2048, Keff=2048, fp16 2-term)
    mma_gemm<0,true><<<dim3(SEQ / 128, SEQ / 128, BATCH), 256, SMEM_B>>>(
        reinterpret_cast<const __nv_bfloat16*>(QA),
        reinterpret_cast<const __nv_bfloat16*>(KB),
        nullptr, sc, nullptr, nullptr, nullptr,
        2 * EMBED, SEQ,
        (long long)SEQ * 2 * EMBED, (long long)SEQ * 2 * EMBED, (long long)SEQ * SEQ,
        0.03125f);

    // softmax + fp16 [hi|lo] split -> PA
    softmax_pa_kernel<<<BATCH * SEQ, 256>>>(sc, PA);

    // GEMM3: out = P @ V   (per batch M=2048, N=1024, Keff=4096, fp16 2-term)
    mma_gemm<0,true><<<dim3(EMBED / 128, SEQ / 128, BATCH), 256, SMEM_B>>>(
        reinterpret_cast<const __nv_bfloat16*>(PA),
        reinterpret_cast<const __nv_bfloat16*>(VB),
        nullptr, out, nullptr, nullptr, nullptr,
        2 * SEQ, EMBED,
        (long long)SEQ * 2 * SEQ, (long long)EMBED * 2 * SEQ, (long long)SEQ * EMBED,
        1.0f);
}

// round 9
// speedup vs baseline: 1.6891x; 1.2061x over previous
#include <cuda_runtime.h>
#include <cuda_bf16.h>
#include <cuda_fp16.h>
#include <math.h>
#include <stdint.h>

#define BATCH   8
#define SEQ     2048
#define EMBED   1024
#define QKVD    3072

// ---------------- scratch (device globals; no allocs allowed) ---------------
__device__ __half g_Vh    [(size_t)BATCH * SEQ * EMBED];   // fp16 V (row-major)
__device__ float  g_scores[(size_t)BATCH * SEQ * SEQ];
__device__ __half g_A1[(size_t)BATCH * SEQ * (2*EMBED)];   // x fp16 [hi|lo]  (A-order)
__device__ __half g_B1[(size_t)QKVD * (2*EMBED)];          // W fp16 [hi|hi]  (B-order)
__device__ __half g_QA[(size_t)BATCH * SEQ * (2*EMBED)];   // Q fp16 [hi|lo]
__device__ __half g_KB[(size_t)BATCH * SEQ * (2*EMBED)];   // K fp16 [hi|hi]
__device__ __half g_VB[(size_t)BATCH * EMBED * (2*SEQ)];   // V^T fp16 [hi|hi]
__device__ __half g_PA[(size_t)BATCH * SEQ * (2*SEQ)];     // probs fp16 [hi|lo]

// ---------------- asm helpers ------------------------------------------------
__device__ __forceinline__ uint32_t smem_u32(const void* p) {
    uint32_t a;
    asm("{ .reg .u64 t; cvta.to.shared.u64 t, %1; cvt.u32.u64 %0, t; }" : "=r"(a) : "l"(p));
    return a;
}
#define CP_ASYNC16(dst, src) \
    asm volatile("cp.async.cg.shared.global [%0], [%1], 16;" :: "r"(dst), "l"(src))
#define CP_COMMIT() asm volatile("cp.async.commit_group;" ::: "memory")
#define CP_WAIT1()  asm volatile("cp.async.wait_group 1;"  ::: "memory")
#define LDMX4(r, addr) \
    asm volatile("ldmatrix.sync.aligned.m8n8.x4.shared.b16 {%0,%1,%2,%3}, [%4];" \
        : "=r"((r)[0]), "=r"((r)[1]), "=r"((r)[2]), "=r"((r)[3]) : "r"(addr))
#define MMA16816_F16(d, a, b) \
    asm volatile("mma.sync.aligned.m16n8k16.row.col.f32.f16.f16.f32 " \
        "{%0,%1,%2,%3}, {%4,%5,%6,%7}, {%8,%9}, {%0,%1,%2,%3};" \
        : "+f"((d)[0]), "+f"((d)[1]), "+f"((d)[2]), "+f"((d)[3]) \
        : "r"((a)[0]), "r"((a)[1]), "r"((a)[2]), "r"((a)[3]), "r"((b)[0]), "r"((b)[1]))

// ---------------- tensor-core GEMM -------------------------------------------
// C[m,n] = alpha * sum_k A[m,k] B[n,k]   (A, B row-major fp16, K-major)
// CTA tile 128x128, K-chunk 64, 3-stage cp.async, single-sync multistage loop.
// 256 threads = 8 warps (2m x 4n), warp tile 64x32, mma.m16n8k16 fp16 -> fp32.
// MODE 0: plain epilogue (alpha scale) -> fp32 C
// MODE 1: fused qkv epilogue (bias + per-region split to QA/KB/Vh, fp16)
#define LDT     72                       // smem row pitch in halves (144 B)
#define ATILE_H (128 * LDT)
#define STAGE_H (2 * ATILE_H)            // A+B tile per stage (halves)
#define NSTAGE  3
#define SMEM_B  (NSTAGE * STAGE_H * 2)   // 110592 bytes

__device__ __forceinline__ void load_chunk(uint32_t sb, int stage,
    const __half* __restrict__ Ag, const __half* __restrict__ Bg,
    int K, int k0, int tid)
{
    const int r = tid >> 1;
    const int c = (tid & 1) * 32;
    const uint32_t base = sb + (uint32_t)stage * (STAGE_H * 2) + (r * LDT + c) * 2;
    const __half* as = Ag + (size_t)r * K + k0 + c;
    const __half* bs = Bg + (size_t)r * K + k0 + c;
    #pragma unroll
    for (int i = 0; i < 4; ++i) CP_ASYNC16(base + i * 16, as + i * 8);
    #pragma unroll
    for (int i = 0; i < 4; ++i) CP_ASYNC16(base + ATILE_H * 2 + i * 16, bs + i * 8);
}

template<int MODE>
__global__ void __launch_bounds__(256, 2) mma_gemm(
    const __half* __restrict__ A, const __half* __restrict__ B,
    const float* __restrict__ bias, float* __restrict__ C,
    __half* __restrict__ QA, __half* __restrict__ KB, __half* __restrict__ Vh,
    int K, int ldc, long long sA, long long sB, long long sC, float alpha)
{
    extern __shared__ char smem[];
    const uint32_t sb = smem_u32(smem);
    const int tid = threadIdx.x;
    const int lane = tid & 31;
    const int wid = tid >> 5;
    const int wm = (wid & 1) * 64;
    const int wn = (wid >> 1) * 32;

    const __half* Ag = A + blockIdx.z * sA + (size_t)(blockIdx.y * 128) * K;
    const __half* Bg = B + blockIdx.z * sB + (size_t)(blockIdx.x * 128) * K;

    const int ar = (lane & 7) + ((lane >> 3) & 1) * 8;
    const int ak = (lane >> 4) * 8;
    const int bn = (lane & 7) + ((lane >> 4) & 1) * 8;
    const int bk = ((lane >> 3) & 1) * 8;

    float acc[4][4][4];
    #pragma unroll
    for (int i = 0; i < 4; ++i)
        #pragma unroll
        for (int j = 0; j < 4; ++j)
            #pragma unroll
            for (int q = 0; q < 4; ++q) acc[i][j][q] = 0.0f;

    const int nch = K / 64;
    load_chunk(sb, 0, Ag, Bg, K, 0, tid);  CP_COMMIT();
    load_chunk(sb, 1, Ag, Bg, K, 64, tid); CP_COMMIT();

    for (int ch = 0; ch < nch; ++ch) {
        const int stage = ch % NSTAGE;
        CP_WAIT1();              // chunk ch resident
        __syncthreads();         // publish cp.async writes; free stage (ch-1)%3

        if (ch + 2 < nch) load_chunk(sb, (ch + 2) % NSTAGE, Ag, Bg, K, (ch + 2) * 64, tid);
        CP_COMMIT();

        const uint32_t abase = sb + (uint32_t)stage * (STAGE_H * 2);
        const uint32_t bbase = abase + ATILE_H * 2;
        #pragma unroll
        for (int s = 0; s < 4; ++s) {
            uint32_t a[4][4];
            #pragma unroll
            for (int mf = 0; mf < 4; ++mf)
                LDMX4(a[mf], abase + ((wm + mf * 16 + ar) * LDT + s * 16 + ak) * 2);
            uint32_t b[2][4];
            #pragma unroll
            for (int n2 = 0; n2 < 2; ++n2)
                LDMX4(b[n2], bbase + ((wn + n2 * 16 + bn) * LDT + s * 16 + bk) * 2);
            #pragma unroll
            for (int mf = 0; mf < 4; ++mf)
                #pragma unroll
                for (int nf = 0; nf < 4; ++nf)
                    MMA16816_F16(acc[mf][nf], a[mf], &b[nf >> 1][(nf & 1) * 2]);
        }
    }

    // ---------------- epilogue ----------------
    const int g  = lane >> 2;
    const int tg = lane & 3;

    if (MODE == 0) {
        float* Cg = C + blockIdx.z * sC;
        #pragma unroll
        for (int mf = 0; mf < 4; ++mf) {
            const int row0 = blockIdx.y * 128 + wm + mf * 16 + g;
            #pragma unroll
            for (int nf = 0; nf < 4; ++nf) {
                const int col = blockIdx.x * 128 + wn + nf * 8 + tg * 2;
                float2 v0 = make_float2(acc[mf][nf][0] * alpha, acc[mf][nf][1] * alpha);
                float2 v1 = make_float2(acc[mf][nf][2] * alpha, acc[mf][nf][3] * alpha);
                *reinterpret_cast<float2*>(Cg + (size_t)row0 * ldc + col) = v0;
                *reinterpret_cast<float2*>(Cg + (size_t)(row0 + 8) * ldc + col) = v1;
            }
        }
    } else {
        const int cblk = blockIdx.x * 128;
        const int region = cblk >> 10;               // 0=Q 1=K 2=V
        #pragma unroll
        for (int mf = 0; mf < 4; ++mf) {
            const int row0 = blockIdx.y * 128 + wm + mf * 16 + g;
            #pragma unroll
            for (int nf = 0; nf < 4; ++nf) {
                const int gcol = cblk + wn + nf * 8 + tg * 2;
                const float2 bb = *reinterpret_cast<const float2*>(bias + gcol);
                float v[2][2];
                v[0][0] = acc[mf][nf][0] + bb.x;  v[0][1] = acc[mf][nf][1] + bb.y;
                v[1][0] = acc[mf][nf][2] + bb.x;  v[1][1] = acc[mf][nf][3] + bb.y;
                const int lcol = gcol & 1023;
                #pragma unroll
                for (int h = 0; h < 2; ++h) {
                    const int r = row0 + h * 8;
                    const __half hi0 = __float2half(v[h][0]);
                    const __half hi1 = __float2half(v[h][1]);
                    const __half2 hp(hi0, hi1);
                    if (region == 2) {               // V: single fp16
                        *reinterpret_cast<__half2*>(Vh + (size_t)r * EMBED + lcol) = hp;
                    } else if (region == 0) {        // QA: hi | lo (exact split)
                        const __half lo0 = __float2half(v[h][0] - __half2float(hi0));
                        const __half lo1 = __float2half(v[h][1] - __half2float(hi1));
                        __half* d0 = QA + (size_t)r * (2 * EMBED) + lcol;
                        *reinterpret_cast<__half2*>(d0)         = hp;
                        *reinterpret_cast<__half2*>(d0 + EMBED) = __half2(lo0, lo1);
                    } else {                         // KB: hi | hi
                        __half* d0 = KB + (size_t)r * (2 * EMBED) + lcol;
                        *reinterpret_cast<__half2*>(d0)         = hp;
                        *reinterpret_cast<__half2*>(d0 + EMBED) = hp;
                    }
                }
            }
        }
    }
}

// ---------------- fp32 -> fp16 split -----------------------------------------
// dst [rows, 2K]: HILO -> [hi|lo] (exact 2-term), else -> [hi|hi] (single term)
template<bool HILO>
__global__ void split_kernel(const float* __restrict__ src, __half* __restrict__ dst,
                             int K, long long nvec)
{
    long long i = blockIdx.x * (long long)blockDim.x + threadIdx.x;
    if (i >= nvec) return;
    long long e = i * 4;
    int row = (int)(e / K), col = (int)(e % K);
    const float4 v = *reinterpret_cast<const float4*>(src + (size_t)row * K + col);
    float vs[4] = { v.x, v.y, v.z, v.w };
    __half h[4];
    #pragma unroll
    for (int j = 0; j < 4; ++j) h[j] = __float2half(vs[j]);
    __half2 hp0(h[0], h[1]), hp1(h[2], h[3]);
    __half* d0 = dst + (size_t)row * 2 * K + col;
    reinterpret_cast<__half2*>(d0)[0] = hp0;
    reinterpret_cast<__half2*>(d0)[1] = hp1;
    if (HILO) {
        __half l[4];
        #pragma unroll
        for (int j = 0; j < 4; ++j) l[j] = __float2half(vs[j] - __half2float(h[j]));
        reinterpret_cast<__half2*>(d0 + K)[0] = __half2(l[0], l[1]);
        reinterpret_cast<__half2*>(d0 + K)[1] = __half2(l[2], l[3]);
    } else {
        reinterpret_cast<__half2*>(d0 + K)[0] = hp0;
        reinterpret_cast<__half2*>(d0 + K)[1] = hp1;
    }
}

// ---------------- V transpose fp16 -> fp16 [hi|hi] (B-order) -----------------
__global__ void vtrans_kernel(const __half* __restrict__ Vh, __half* __restrict__ VB)
{
    __shared__ __half t[32][34];
    const int b = blockIdx.z;
    const int n0 = blockIdx.x * 32, e0 = blockIdx.y * 32;
    const int tx = threadIdx.x, ty = threadIdx.y;
    const __half* src = Vh + (size_t)b * SEQ * EMBED;
    #pragma unroll
    for (int i = 0; i < 4; ++i)
        t[ty + 8 * i][tx] = src[(size_t)(n0 + ty + 8 * i) * EMBED + e0 + tx];
    __syncthreads();
    __half* dst = VB + (size_t)b * EMBED * (2 * SEQ);
    #pragma unroll
    for (int i = 0; i < 4; ++i) {
        const __half h = t[tx][ty + 8 * i];
        const size_t base = (size_t)(e0 + ty + 8 * i) * (2 * SEQ) + n0 + tx;
        dst[base]       = h;
        dst[base + SEQ] = h;
    }
}

// ---------------- softmax + prob split to fp16 (A-order [hi|lo]) -------------
__global__ void softmax_pa_kernel(const float* __restrict__ s, __half* __restrict__ PA)
{
    __shared__ float row[SEQ];
    __shared__ float red[8];
    const int tid = threadIdx.x;
    const float4* p4 = reinterpret_cast<const float4*>(s + (size_t)blockIdx.x * SEQ);
    float4* r4 = reinterpret_cast<float4*>(row);

    float lmax = -3.4e38f;
    #pragma unroll
    for (int it = 0; it < 2; ++it) {
        const float4 t = p4[tid + it * 256];
        r4[tid + it * 256] = t;
        lmax = fmaxf(lmax, fmaxf(fmaxf(t.x, t.y), fmaxf(t.z, t.w)));
    }
    #pragma unroll
    for (int o = 16; o; o >>= 1) lmax = fmaxf(lmax, __shfl_xor_sync(0xffffffffu, lmax, o));
    if ((tid & 31) == 0) red[tid >> 5] = lmax;
    __syncthreads();
    const float rmax = fmaxf(fmaxf(fmaxf(red[0], red[1]), fmaxf(red[2], red[3])),
                             fmaxf(fmaxf(red[4], red[5]), fmaxf(red[6], red[7])));
    __syncthreads();

    float lsum = 0.0f;
    #pragma unroll
    for (int it = 0; it < 2; ++it) {
        float4 t = r4[tid + it * 256];
        t.x = expf(t.x - rmax); t.y = expf(t.y - rmax);
        t.z = expf(t.z - rmax); t.w = expf(t.w - rmax);
        r4[tid + it * 256] = t;
        lsum += (t.x + t.y) + (t.z + t.w);
    }
    #pragma unroll
    for (int o = 16; o; o >>= 1) lsum += __shfl_xor_sync(0xffffffffu, lsum, o);
    if ((tid & 31) == 0) red[tid >> 5] = lsum;
    __syncthreads();
    const float inv = 1.0f / (((red[0] + red[1]) + (red[2] + red[3])) +
                              ((red[4] + red[5]) + (red[6] + red[7])));

    __half* pa = PA + (size_t)blockIdx.x * (2 * SEQ);
    #pragma unroll
    for (int it = 0; it < 2; ++it) {
        float4 t = r4[tid + it * 256];
        t.x *= inv; t.y *= inv; t.z *= inv; t.w *= inv;
        float vs[4] = { t.x, t.y, t.z, t.w };
        __half h[4], l[4];
        #pragma unroll
        for (int j = 0; j < 4; ++j) {
            h[j] = __float2half(vs[j]);
            l[j] = __float2half(vs[j] - __half2float(h[j]));
        }
        const int idx = (tid + it * 256) * 4;
        __half2 hp0(h[0], h[1]), hp1(h[2], h[3]);
        __half2 lp0(l[0], l[1]), lp1(l[2], l[3]);
        reinterpret_cast<__half2*>(pa + idx)[0] = hp0;
        reinterpret_cast<__half2*>(pa + idx)[1] = hp1;
        reinterpret_cast<__half2*>(pa + SEQ + idx)[0] = lp0;
        reinterpret_cast<__half2*>(pa + SEQ + idx)[1] = lp1;
    }
}

// -----------------------------------------------------------------------------
extern "C" void kernel_launch(void* const* d_in, const int* in_sizes, int n_in,
                              void* d_out, int out_size)
{
    const float* x = (const float*)d_in[0];
    const float* W = (const float*)d_in[1];
    const float* b = (const float*)d_in[2];
    float* out = (float*)d_out;

    float *sc;
    __half *Vh, *A1, *B1, *QA, *KB, *VB, *PA;
    { void* p; cudaGetSymbolAddress(&p, g_Vh);     Vh = (__half*)p; }
    { void* p; cudaGetSymbolAddress(&p, g_scores); sc = (float*)p; }
    { void* p; cudaGetSymbolAddress(&p, g_A1); A1 = (__half*)p; }
    { void* p; cudaGetSymbolAddress(&p, g_B1); B1 = (__half*)p; }
    { void* p; cudaGetSymbolAddress(&p, g_QA); QA = (__half*)p; }
    { void* p; cudaGetSymbolAddress(&p, g_KB); KB = (__half*)p; }
    { void* p; cudaGetSymbolAddress(&p, g_VB); VB = (__half*)p; }
    { void* p; cudaGetSymbolAddress(&p, g_PA); PA = (__half*)p; }

    cudaFuncSetAttribute(mma_gemm<0>, cudaFuncAttributeMaxDynamicSharedMemorySize, SMEM_B);
    cudaFuncSetAttribute(mma_gemm<1>, cudaFuncAttributeMaxDynamicSharedMemorySize, SMEM_B);

    const long long MN = (long long)BATCH * SEQ;   // 16384

    // input splits: x -> A1 fp16 [hi|lo], W -> B1 fp16 [hi|hi]
    split_kernel<true ><<<(unsigned)((MN * EMBED / 4 + 255) / 256), 256>>>(
        x, A1, EMBED, MN * EMBED / 4);
    split_kernel<false><<<(unsigned)(((long long)QKVD * EMBED / 4 + 255) / 256), 256>>>(
        W, B1, EMBED, (long long)QKVD * EMBED / 4);

    // GEMM1 (fused): qkv = x @ W^T + b  (Keff=2048, fp16 2-term)
    //   -> QA fp16[hi|lo], KB fp16[hi|hi], Vh fp16
    mma_gemm<1><<<dim3(QKVD / 128, (unsigned)(MN / 128), 1), 256, SMEM_B>>>(
        A1, B1, b, nullptr, QA, KB, Vh,
        2 * EMBED, 0, 0, 0, 0, 1.0f);

    // V transpose -> fp16 [hi|hi]
    vtrans_kernel<<<dim3(SEQ / 32, EMBED / 32, BATCH), dim3(32, 8)>>>(Vh, VB);

    // GEMM2: scores = Q @ K^T / 32   (per batch M=N=2048, Keff=2048, fp16 2-term)
    mma_gemm<0><<<dim3(SEQ / 128, SEQ / 128, BATCH), 256, SMEM_B>>>(
        QA, KB, nullptr, sc, nullptr, nullptr, nullptr,
        2 * EMBED, SEQ,
        (long long)SEQ * 2 * EMBED, (long long)SEQ * 2 * EMBED, (long long)SEQ * SEQ,
        0.03125f);

    // softmax + fp16 [hi|lo] split -> PA
    softmax_pa_kernel<<<BATCH * SEQ, 256>>>(sc, PA);

    // GEMM3: out = P @ V   (per batch M=2048, N=1024, Keff=4096, fp16 2-term)
    mma_gemm<0><<<dim3(EMBED / 128, SEQ / 128, BATCH), 256, SMEM_B>>>(
        PA, VB, nullptr, out, nullptr, nullptr, nullptr,
        2 * SEQ, EMBED,
        (long long)SEQ * 2 * SEQ, (long long)EMBED * 2 * SEQ, (long long)SEQ * EMBED,
        1.0f);
}

// round 10
// speedup vs baseline: 1.9592x; 1.1599x over previous
#include <cuda_runtime.h>
#include <cuda_bf16.h>
#include <cuda_fp16.h>
#include <math.h>
#include <stdint.h>

#define BATCH   8
#define SEQ     2048
#define EMBED   1024
#define QKVD    3072

// ---------------- scratch (device globals; no allocs allowed) ---------------
__device__ __half g_Vh    [(size_t)BATCH * SEQ * EMBED];   // fp16 V (row-major)
__device__ float  g_scores[(size_t)BATCH * SEQ * SEQ];
__device__ __half g_A1[(size_t)BATCH * SEQ * (2*EMBED)];   // x fp16 [hi|lo]  (A-order)
__device__ __half g_B1[(size_t)QKVD * (2*EMBED)];          // W fp16 [hi|hi]  (B-order)
__device__ __half g_QA[(size_t)BATCH * SEQ * (2*EMBED)];   // Q fp16 [hi|lo]
__device__ __half g_KB[(size_t)BATCH * SEQ * (2*EMBED)];   // K fp16 [hi|hi]
__device__ __half g_VB[(size_t)BATCH * EMBED * SEQ];       // V^T fp16 (single)
__device__ __half g_PA[(size_t)BATCH * SEQ * SEQ];         // probs fp16 (single)

// ---------------- asm helpers ------------------------------------------------
__device__ __forceinline__ uint32_t smem_u32(const void* p) {
    uint32_t a;
    asm("{ .reg .u64 t; cvta.to.shared.u64 t, %1; cvt.u32.u64 %0, t; }" : "=r"(a) : "l"(p));
    return a;
}
#define CP_ASYNC16(dst, src) \
    asm volatile("cp.async.cg.shared.global [%0], [%1], 16;" :: "r"(dst), "l"(src))
#define CP_COMMIT() asm volatile("cp.async.commit_group;" ::: "memory")
#define CP_WAIT1()  asm volatile("cp.async.wait_group 1;"  ::: "memory")
#define LDMX4(r, addr) \
    asm volatile("ldmatrix.sync.aligned.m8n8.x4.shared.b16 {%0,%1,%2,%3}, [%4];" \
        : "=r"((r)[0]), "=r"((r)[1]), "=r"((r)[2]), "=r"((r)[3]) : "r"(addr))
#define MMA16816_F16(d, a, b) \
    asm volatile("mma.sync.aligned.m16n8k16.row.col.f32.f16.f16.f32 " \
        "{%0,%1,%2,%3}, {%4,%5,%6,%7}, {%8,%9}, {%0,%1,%2,%3};" \
        : "+f"((d)[0]), "+f"((d)[1]), "+f"((d)[2]), "+f"((d)[3]) \
        : "r"((a)[0]), "r"((a)[1]), "r"((a)[2]), "r"((a)[3]), "r"((b)[0]), "r"((b)[1]))

// ---------------- tensor-core GEMM -------------------------------------------
// C[m,n] = alpha * sum_k A[m,k] B[n,k]   (A, B row-major fp16, K-major)
// CTA tile 128x128, K-chunk 64, 3-stage cp.async, single-sync multistage loop.
// 256 threads = 8 warps (2m x 4n), warp tile 64x32, mma.m16n8k16 fp16 -> fp32.
// MODE 0: plain epilogue (alpha scale) -> fp32 C
// MODE 1: fused qkv epilogue (bias + per-region split to QA/KB/Vh, fp16)
#define LDT     72                       // smem row pitch in halves (144 B)
#define ATILE_H (128 * LDT)
#define STAGE_H (2 * ATILE_H)            // A+B tile per stage (halves)
#define NSTAGE  3
#define SMEM_B  (NSTAGE * STAGE_H * 2)   // 110592 bytes

__device__ __forceinline__ void load_chunk(uint32_t sb, int stage,
    const __half* __restrict__ Ag, const __half* __restrict__ Bg,
    int K, int k0, int tid)
{
    const int r = tid >> 1;
    const int c = (tid & 1) * 32;
    const uint32_t base = sb + (uint32_t)stage * (STAGE_H * 2) + (r * LDT + c) * 2;
    const __half* as = Ag + (size_t)r * K + k0 + c;
    const __half* bs = Bg + (size_t)r * K + k0 + c;
    #pragma unroll
    for (int i = 0; i < 4; ++i) CP_ASYNC16(base + i * 16, as + i * 8);
    #pragma unroll
    for (int i = 0; i < 4; ++i) CP_ASYNC16(base + ATILE_H * 2 + i * 16, bs + i * 8);
}

template<int MODE>
__global__ void __launch_bounds__(256, 2) mma_gemm(
    const __half* __restrict__ A, const __half* __restrict__ B,
    const float* __restrict__ bias, float* __restrict__ C,
    __half* __restrict__ QA, __half* __restrict__ KB, __half* __restrict__ Vh,
    int K, int ldc, long long sA, long long sB, long long sC, float alpha)
{
    extern __shared__ char smem[];
    const uint32_t sb = smem_u32(smem);
    const int tid = threadIdx.x;
    const int lane = tid & 31;
    const int wid = tid >> 5;
    const int wm = (wid & 1) * 64;
    const int wn = (wid >> 1) * 32;

    const __half* Ag = A + blockIdx.z * sA + (size_t)(blockIdx.y * 128) * K;
    const __half* Bg = B + blockIdx.z * sB + (size_t)(blockIdx.x * 128) * K;

    const int ar = (lane & 7) + ((lane >> 3) & 1) * 8;
    const int ak = (lane >> 4) * 8;
    const int bn = (lane & 7) + ((lane >> 4) & 1) * 8;
    const int bk = ((lane >> 3) & 1) * 8;

    float acc[4][4][4];
    #pragma unroll
    for (int i = 0; i < 4; ++i)
        #pragma unroll
        for (int j = 0; j < 4; ++j)
            #pragma unroll
            for (int q = 0; q < 4; ++q) acc[i][j][q] = 0.0f;

    const int nch = K / 64;
    load_chunk(sb, 0, Ag, Bg, K, 0, tid);  CP_COMMIT();
    load_chunk(sb, 1, Ag, Bg, K, 64, tid); CP_COMMIT();

    for (int ch = 0; ch < nch; ++ch) {
        const int stage = ch % NSTAGE;
        CP_WAIT1();              // chunk ch resident
        __syncthreads();         // publish cp.async writes; free stage (ch-1)%3

        if (ch + 2 < nch) load_chunk(sb, (ch + 2) % NSTAGE, Ag, Bg, K, (ch + 2) * 64, tid);
        CP_COMMIT();

        const uint32_t abase = sb + (uint32_t)stage * (STAGE_H * 2);
        const uint32_t bbase = abase + ATILE_H * 2;
        #pragma unroll
        for (int s = 0; s < 4; ++s) {
            uint32_t a[4][4];
            #pragma unroll
            for (int mf = 0; mf < 4; ++mf)
                LDMX4(a[mf], abase + ((wm + mf * 16 + ar) * LDT + s * 16 + ak) * 2);
            uint32_t b[2][4];
            #pragma unroll
            for (int n2 = 0; n2 < 2; ++n2)
                LDMX4(b[n2], bbase + ((wn + n2 * 16 + bn) * LDT + s * 16 + bk) * 2);
            #pragma unroll
            for (int mf = 0; mf < 4; ++mf)
                #pragma unroll
                for (int nf = 0; nf < 4; ++nf)
                    MMA16816_F16(acc[mf][nf], a[mf], &b[nf >> 1][(nf & 1) * 2]);
        }
    }

    // ---------------- epilogue ----------------
    const int g  = lane >> 2;
    const int tg = lane & 3;

    if (MODE == 0) {
        float* Cg = C + blockIdx.z * sC;
        #pragma unroll
        for (int mf = 0; mf < 4; ++mf) {
            const int row0 = blockIdx.y * 128 + wm + mf * 16 + g;
            #pragma unroll
            for (int nf = 0; nf < 4; ++nf) {
                const int col = blockIdx.x * 128 + wn + nf * 8 + tg * 2;
                float2 v0 = make_float2(acc[mf][nf][0] * alpha, acc[mf][nf][1] * alpha);
                float2 v1 = make_float2(acc[mf][nf][2] * alpha, acc[mf][nf][3] * alpha);
                *reinterpret_cast<float2*>(Cg + (size_t)row0 * ldc + col) = v0;
                *reinterpret_cast<float2*>(Cg + (size_t)(row0 + 8) * ldc + col) = v1;
            }
        }
    } else {
        const int cblk = blockIdx.x * 128;
        const int region = cblk >> 10;               // 0=Q 1=K 2=V
        #pragma unroll
        for (int mf = 0; mf < 4; ++mf) {
            const int row0 = blockIdx.y * 128 + wm + mf * 16 + g;
            #pragma unroll
            for (int nf = 0; nf < 4; ++nf) {
                const int gcol = cblk + wn + nf * 8 + tg * 2;
                const float2 bb = *reinterpret_cast<const float2*>(bias + gcol);
                float v[2][2];
                v[0][0] = acc[mf][nf][0] + bb.x;  v[0][1] = acc[mf][nf][1] + bb.y;
                v[1][0] = acc[mf][nf][2] + bb.x;  v[1][1] = acc[mf][nf][3] + bb.y;
                const int lcol = gcol & 1023;
                #pragma unroll
                for (int h = 0; h < 2; ++h) {
                    const int r = row0 + h * 8;
                    const __half hi0 = __float2half(v[h][0]);
                    const __half hi1 = __float2half(v[h][1]);
                    const __half2 hp(hi0, hi1);
                    if (region == 2) {               // V: single fp16
                        *reinterpret_cast<__half2*>(Vh + (size_t)r * EMBED + lcol) = hp;
                    } else if (region == 0) {        // QA: hi | lo (exact split)
                        const __half lo0 = __float2half(v[h][0] - __half2float(hi0));
                        const __half lo1 = __float2half(v[h][1] - __half2float(hi1));
                        __half* d0 = QA + (size_t)r * (2 * EMBED) + lcol;
                        *reinterpret_cast<__half2*>(d0)         = hp;
                        *reinterpret_cast<__half2*>(d0 + EMBED) = __half2(lo0, lo1);
                    } else {                         // KB: hi | hi
                        __half* d0 = KB + (size_t)r * (2 * EMBED) + lcol;
                        *reinterpret_cast<__half2*>(d0)         = hp;
                        *reinterpret_cast<__half2*>(d0 + EMBED) = hp;
                    }
                }
            }
        }
    }
}

// ---------------- fp32 -> fp16 split -----------------------------------------
// dst [rows, 2K]: HILO -> [hi|lo] (exact 2-term), else -> [hi|hi] (single term)
template<bool HILO>
__global__ void split_kernel(const float* __restrict__ src, __half* __restrict__ dst,
                             int K, long long nvec)
{
    long long i = blockIdx.x * (long long)blockDim.x + threadIdx.x;
    if (i >= nvec) return;
    long long e = i * 4;
    int row = (int)(e / K), col = (int)(e % K);
    const float4 v = *reinterpret_cast<const float4*>(src + (size_t)row * K + col);
    float vs[4] = { v.x, v.y, v.z, v.w };
    __half h[4];
    #pragma unroll
    for (int j = 0; j < 4; ++j) h[j] = __float2half(vs[j]);
    __half2 hp0(h[0], h[1]), hp1(h[2], h[3]);
    __half* d0 = dst + (size_t)row * 2 * K + col;
    reinterpret_cast<__half2*>(d0)[0] = hp0;
    reinterpret_cast<__half2*>(d0)[1] = hp1;
    if (HILO) {
        __half l[4];
        #pragma unroll
        for (int j = 0; j < 4; ++j) l[j] = __float2half(vs[j] - __half2float(h[j]));
        reinterpret_cast<__half2*>(d0 + K)[0] = __half2(l[0], l[1]);
        reinterpret_cast<__half2*>(d0 + K)[1] = __half2(l[2], l[3]);
    } else {
        reinterpret_cast<__half2*>(d0 + K)[0] = hp0;
        reinterpret_cast<__half2*>(d0 + K)[1] = hp1;
    }
}

// ---------------- V transpose fp16 -> fp16 (B-order, single) -----------------
__global__ void vtrans_kernel(const __half* __restrict__ Vh, __half* __restrict__ VB)
{
    __shared__ __half t[32][34];
    const int b = blockIdx.z;
    const int n0 = blockIdx.x * 32, e0 = blockIdx.y * 32;
    const int tx = threadIdx.x, ty = threadIdx.y;
    const __half* src = Vh + (size_t)b * SEQ * EMBED;
    #pragma unroll
    for (int i = 0; i < 4; ++i)
        t[ty + 8 * i][tx] = src[(size_t)(n0 + ty + 8 * i) * EMBED + e0 + tx];
    __syncthreads();
    __half* dst = VB + (size_t)b * EMBED * SEQ;
    #pragma unroll
    for (int i = 0; i < 4; ++i)
        dst[(size_t)(e0 + ty + 8 * i) * SEQ + n0 + tx] = t[tx][ty + 8 * i];
}

// ---------------- softmax -> fp16 probs (single term) ------------------------
__global__ void softmax_pa_kernel(const float* __restrict__ s, __half* __restrict__ PA)
{
    __shared__ float row[SEQ];
    __shared__ float red[8];
    const int tid = threadIdx.x;
    const float4* p4 = reinterpret_cast<const float4*>(s + (size_t)blockIdx.x * SEQ);
    float4* r4 = reinterpret_cast<float4*>(row);

    float lmax = -3.4e38f;
    #pragma unroll
    for (int it = 0; it < 2; ++it) {
        const float4 t = p4[tid + it * 256];
        r4[tid + it * 256] = t;
        lmax = fmaxf(lmax, fmaxf(fmaxf(t.x, t.y), fmaxf(t.z, t.w)));
    }
    #pragma unroll
    for (int o = 16; o; o >>= 1) lmax = fmaxf(lmax, __shfl_xor_sync(0xffffffffu, lmax, o));
    if ((tid & 31) == 0) red[tid >> 5] = lmax;
    __syncthreads();
    const float rmax = fmaxf(fmaxf(fmaxf(red[0], red[1]), fmaxf(red[2], red[3])),
                             fmaxf(fmaxf(red[4], red[5]), fmaxf(red[6], red[7])));
    __syncthreads();

    float lsum = 0.0f;
    #pragma unroll
    for (int it = 0; it < 2; ++it) {
        float4 t = r4[tid + it * 256];
        t.x = expf(t.x - rmax); t.y = expf(t.y - rmax);
        t.z = expf(t.z - rmax); t.w = expf(t.w - rmax);
        r4[tid + it * 256] = t;
        lsum += (t.x + t.y) + (t.z + t.w);
    }
    #pragma unroll
    for (int o = 16; o; o >>= 1) lsum += __shfl_xor_sync(0xffffffffu, lsum, o);
    if ((tid & 31) == 0) red[tid >> 5] = lsum;
    __syncthreads();
    const float inv = 1.0f / (((red[0] + red[1]) + (red[2] + red[3])) +
                              ((red[4] + red[5]) + (red[6] + red[7])));

    __half* pa = PA + (size_t)blockIdx.x * SEQ;
    #pragma unroll
    for (int it = 0; it < 2; ++it) {
        float4 t = r4[tid + it * 256];
        const int idx = (tid + it * 256) * 4;
        __half2 hp0(__float2half(t.x * inv), __float2half(t.y * inv));
        __half2 hp1(__float2half(t.z * inv), __float2half(t.w * inv));
        reinterpret_cast<__half2*>(pa + idx)[0] = hp0;
        reinterpret_cast<__half2*>(pa + idx)[1] = hp1;
    }
}

// -----------------------------------------------------------------------------
extern "C" void kernel_launch(void* const* d_in, const int* in_sizes, int n_in,
                              void* d_out, int out_size)
{
    const float* x = (const float*)d_in[0];
    const float* W = (const float*)d_in[1];
    const float* b = (const float*)d_in[2];
    float* out = (float*)d_out;

    float *sc;
    __half *Vh, *A1, *B1, *QA, *KB, *VB, *PA;
    { void* p; cudaGetSymbolAddress(&p, g_Vh);     Vh = (__half*)p; }
    { void* p; cudaGetSymbolAddress(&p, g_scores); sc = (float*)p; }
    { void* p; cudaGetSymbolAddress(&p, g_A1); A1 = (__half*)p; }
    { void* p; cudaGetSymbolAddress(&p, g_B1); B1 = (__half*)p; }
    { void* p; cudaGetSymbolAddress(&p, g_QA); QA = (__half*)p; }
    { void* p; cudaGetSymbolAddress(&p, g_KB); KB = (__half*)p; }
    { void* p; cudaGetSymbolAddress(&p, g_VB); VB = (__half*)p; }
    { void* p; cudaGetSymbolAddress(&p, g_PA); PA = (__half*)p; }

    cudaFuncSetAttribute(mma_gemm<0>, cudaFuncAttributeMaxDynamicSharedMemorySize, SMEM_B);
    cudaFuncSetAttribute(mma_gemm<1>, cudaFuncAttributeMaxDynamicSharedMemorySize, SMEM_B);

    const long long MN = (long long)BATCH * SEQ;   // 16384

    // input splits: x -> A1 fp16 [hi|lo], W -> B1 fp16 [hi|hi]
    split_kernel<true ><<<(unsigned)((MN * EMBED / 4 + 255) / 256), 256>>>(
        x, A1, EMBED, MN * EMBED / 4);
    split_kernel<false><<<(unsigned)(((long long)QKVD * EMBED / 4 + 255) / 256), 256>>>(
        W, B1, EMBED, (long long)QKVD * EMBED / 4);

    // GEMM1 (fused): qkv = x @ W^T + b  (Keff=2048, fp16 2-term)
    //   -> QA fp16[hi|lo], KB fp16[hi|hi], Vh fp16
    mma_gemm<1><<<dim3(QKVD / 128, (unsigned)(MN / 128), 1), 256, SMEM_B>>>(
        A1, B1, b, nullptr, QA, KB, Vh,
        2 * EMBED, 0, 0, 0, 0, 1.0f);

    // V transpose -> fp16 single
    vtrans_kernel<<<dim3(SEQ / 32, EMBED / 32, BATCH), dim3(32, 8)>>>(Vh, VB);

    // GEMM2: scores = Q @ K^T / 32   (per batch M=N=2048, Keff=2048, fp16 2-term)
    mma_gemm<0><<<dim3(SEQ / 128, SEQ / 128, BATCH), 256, SMEM_B>>>(
        QA, KB, nullptr, sc, nullptr, nullptr, nullptr,
        2 * EMBED, SEQ,
        (long long)SEQ * 2 * EMBED, (long long)SEQ * 2 * EMBED, (long long)SEQ * SEQ,
        0.03125f);

    // softmax -> fp16 probs (single term)
    softmax_pa_kernel<<<BATCH * SEQ, 256>>>(sc, PA);

    // GEMM3: out = P @ V   (per batch M=2048, N=1024, Keff=2048, fp16 single)
    mma_gemm<0><<<dim3(EMBED / 128, SEQ / 128, BATCH), 256, SMEM_B>>>(
        PA, VB, nullptr, out, nullptr, nullptr, nullptr,
        SEQ, EMBED,
        (long long)SEQ * SEQ, (long long)EMBED * SEQ, (long long)SEQ * EMBED,
        1.0f);
}

// round 11
// speedup vs baseline: 2.3180x; 1.1832x over previous
#include <cuda_runtime.h>
#include <cuda_bf16.h>
#include <cuda_fp16.h>
#include <math.h>
#include <stdint.h>

#define BATCH   8
#define SEQ     2048
#define EMBED   1024
#define QKVD    3072

// ---------------- scratch (device globals; no allocs allowed) ---------------
__device__ __half g_Vh    [(size_t)BATCH * SEQ * EMBED];   // fp16 V (row-major)
__device__ float  g_scores[(size_t)BATCH * SEQ * SEQ];
__device__ __half g_A1[(size_t)BATCH * SEQ * (2*EMBED)];   // x fp16 [hi|lo]  (A-order)
__device__ __half g_B1[(size_t)QKVD * (2*EMBED)];          // W fp16 [hi|hi]  (B-order)
__device__ __half g_QA[(size_t)BATCH * SEQ * EMBED];       // Q fp16 (single)
__device__ __half g_KB[(size_t)BATCH * SEQ * EMBED];       // K fp16 (single)
__device__ __half g_VB[(size_t)BATCH * EMBED * SEQ];       // V^T fp16 (single)
__device__ __half g_PA[(size_t)BATCH * SEQ * SEQ];         // probs fp16 (single)

// ---------------- asm helpers ------------------------------------------------
__device__ __forceinline__ uint32_t smem_u32(const void* p) {
    uint32_t a;
    asm("{ .reg .u64 t; cvta.to.shared.u64 t, %1; cvt.u32.u64 %0, t; }" : "=r"(a) : "l"(p));
    return a;
}
#define CP_ASYNC16(dst, src) \
    asm volatile("cp.async.cg.shared.global [%0], [%1], 16;" :: "r"(dst), "l"(src))
#define CP_COMMIT() asm volatile("cp.async.commit_group;" ::: "memory")
#define CP_WAIT1()  asm volatile("cp.async.wait_group 1;"  ::: "memory")
#define LDMX4(r, addr) \
    asm volatile("ldmatrix.sync.aligned.m8n8.x4.shared.b16 {%0,%1,%2,%3}, [%4];" \
        : "=r"((r)[0]), "=r"((r)[1]), "=r"((r)[2]), "=r"((r)[3]) : "r"(addr))
#define MMA16816_F16(d, a, b) \
    asm volatile("mma.sync.aligned.m16n8k16.row.col.f32.f16.f16.f32 " \
        "{%0,%1,%2,%3}, {%4,%5,%6,%7}, {%8,%9}, {%0,%1,%2,%3};" \
        : "+f"((d)[0]), "+f"((d)[1]), "+f"((d)[2]), "+f"((d)[3]) \
        : "r"((a)[0]), "r"((a)[1]), "r"((a)[2]), "r"((a)[3]), "r"((b)[0]), "r"((b)[1]))

// ---------------- tensor-core GEMM -------------------------------------------
// C[m,n] = alpha * sum_k A[m,k] B[n,k]   (A, B row-major fp16, K-major)
// CTA tile 128x128, K-chunk 64, 3-stage cp.async, single-sync multistage loop.
// 256 threads = 8 warps (2m x 4n), warp tile 64x32, mma.m16n8k16 fp16 -> fp32.
// MODE 0: plain epilogue (alpha scale) -> fp32 C
// MODE 1: fused qkv epilogue (bias + single-fp16 writes to QA/KB/Vh)
#define LDT     72                       // smem row pitch in halves (144 B)
#define ATILE_H (128 * LDT)
#define STAGE_H (2 * ATILE_H)            // A+B tile per stage (halves)
#define NSTAGE  3
#define SMEM_B  (NSTAGE * STAGE_H * 2)   // 110592 bytes

__device__ __forceinline__ void load_chunk(uint32_t sb, int stage,
    const __half* __restrict__ Ag, const __half* __restrict__ Bg,
    int K, int k0, int tid)
{
    const int r = tid >> 1;
    const int c = (tid & 1) * 32;
    const uint32_t base = sb + (uint32_t)stage * (STAGE_H * 2) + (r * LDT + c) * 2;
    const __half* as = Ag + (size_t)r * K + k0 + c;
    const __half* bs = Bg + (size_t)r * K + k0 + c;
    #pragma unroll
    for (int i = 0; i < 4; ++i) CP_ASYNC16(base + i * 16, as + i * 8);
    #pragma unroll
    for (int i = 0; i < 4; ++i) CP_ASYNC16(base + ATILE_H * 2 + i * 16, bs + i * 8);
}

template<int MODE>
__global__ void __launch_bounds__(256, 2) mma_gemm(
    const __half* __restrict__ A, const __half* __restrict__ B,
    const float* __restrict__ bias, float* __restrict__ C,
    __half* __restrict__ QA, __half* __restrict__ KB, __half* __restrict__ Vh,
    int K, int ldc, long long sA, long long sB, long long sC, float alpha)
{
    extern __shared__ char smem[];
    const uint32_t sb = smem_u32(smem);
    const int tid = threadIdx.x;
    const int lane = tid & 31;
    const int wid = tid >> 5;
    const int wm = (wid & 1) * 64;
    const int wn = (wid >> 1) * 32;

    const __half* Ag = A + blockIdx.z * sA + (size_t)(blockIdx.y * 128) * K;
    const __half* Bg = B + blockIdx.z * sB + (size_t)(blockIdx.x * 128) * K;

    const int ar = (lane & 7) + ((lane >> 3) & 1) * 8;
    const int ak = (lane >> 4) * 8;
    const int bn = (lane & 7) + ((lane >> 4) & 1) * 8;
    const int bk = ((lane >> 3) & 1) * 8;

    float acc[4][4][4];
    #pragma unroll
    for (int i = 0; i < 4; ++i)
        #pragma unroll
        for (int j = 0; j < 4; ++j)
            #pragma unroll
            for (int q = 0; q < 4; ++q) acc[i][j][q] = 0.0f;

    const int nch = K / 64;
    load_chunk(sb, 0, Ag, Bg, K, 0, tid);  CP_COMMIT();
    load_chunk(sb, 1, Ag, Bg, K, 64, tid); CP_COMMIT();

    for (int ch = 0; ch < nch; ++ch) {
        const int stage = ch % NSTAGE;
        CP_WAIT1();              // chunk ch resident
        __syncthreads();         // publish cp.async writes; free stage (ch-1)%3

        if (ch + 2 < nch) load_chunk(sb, (ch + 2) % NSTAGE, Ag, Bg, K, (ch + 2) * 64, tid);
        CP_COMMIT();

        const uint32_t abase = sb + (uint32_t)stage * (STAGE_H * 2);
        const uint32_t bbase = abase + ATILE_H * 2;
        #pragma unroll
        for (int s = 0; s < 4; ++s) {
            uint32_t a[4][4];
            #pragma unroll
            for (int mf = 0; mf < 4; ++mf)
                LDMX4(a[mf], abase + ((wm + mf * 16 + ar) * LDT + s * 16 + ak) * 2);
            uint32_t b[2][4];
            #pragma unroll
            for (int n2 = 0; n2 < 2; ++n2)
                LDMX4(b[n2], bbase + ((wn + n2 * 16 + bn) * LDT + s * 16 + bk) * 2);
            #pragma unroll
            for (int mf = 0; mf < 4; ++mf)
                #pragma unroll
                for (int nf = 0; nf < 4; ++nf)
                    MMA16816_F16(acc[mf][nf], a[mf], &b[nf >> 1][(nf & 1) * 2]);
        }
    }

    // ---------------- epilogue ----------------
    const int g  = lane >> 2;
    const int tg = lane & 3;

    if (MODE == 0) {
        float* Cg = C + blockIdx.z * sC;
        #pragma unroll
        for (int mf = 0; mf < 4; ++mf) {
            const int row0 = blockIdx.y * 128 + wm + mf * 16 + g;
            #pragma unroll
            for (int nf = 0; nf < 4; ++nf) {
                const int col = blockIdx.x * 128 + wn + nf * 8 + tg * 2;
                float2 v0 = make_float2(acc[mf][nf][0] * alpha, acc[mf][nf][1] * alpha);
                float2 v1 = make_float2(acc[mf][nf][2] * alpha, acc[mf][nf][3] * alpha);
                *reinterpret_cast<float2*>(Cg + (size_t)row0 * ldc + col) = v0;
                *reinterpret_cast<float2*>(Cg + (size_t)(row0 + 8) * ldc + col) = v1;
            }
        }
    } else {
        const int cblk = blockIdx.x * 128;
        const int region = cblk >> 10;               // 0=Q 1=K 2=V
        __half* dst = (region == 0) ? QA : (region == 1) ? KB : Vh;
        #pragma unroll
        for (int mf = 0; mf < 4; ++mf) {
            const int row0 = blockIdx.y * 128 + wm + mf * 16 + g;
            #pragma unroll
            for (int nf = 0; nf < 4; ++nf) {
                const int gcol = cblk + wn + nf * 8 + tg * 2;
                const float2 bb = *reinterpret_cast<const float2*>(bias + gcol);
                const int lcol = gcol & 1023;
                #pragma unroll
                for (int h = 0; h < 2; ++h) {
                    const int r = row0 + h * 8;
                    const __half2 hp(__float2half(acc[mf][nf][h * 2 + 0] + bb.x),
                                     __float2half(acc[mf][nf][h * 2 + 1] + bb.y));
                    *reinterpret_cast<__half2*>(dst + (size_t)r * EMBED + lcol) = hp;
                }
            }
        }
    }
}

// ---------------- fp32 -> fp16 split -----------------------------------------
// dst [rows, 2K]: HILO -> [hi|lo] (exact 2-term), else -> [hi|hi] (single term)
template<bool HILO>
__global__ void split_kernel(const float* __restrict__ src, __half* __restrict__ dst,
                             int K, long long nvec)
{
    long long i = blockIdx.x * (long long)blockDim.x + threadIdx.x;
    if (i >= nvec) return;
    long long e = i * 4;
    int row = (int)(e / K), col = (int)(e % K);
    const float4 v = *reinterpret_cast<const float4*>(src + (size_t)row * K + col);
    float vs[4] = { v.x, v.y, v.z, v.w };
    __half h[4];
    #pragma unroll
    for (int j = 0; j < 4; ++j) h[j] = __float2half(vs[j]);
    __half2 hp0(h[0], h[1]), hp1(h[2], h[3]);
    __half* d0 = dst + (size_t)row * 2 * K + col;
    reinterpret_cast<__half2*>(d0)[0] = hp0;
    reinterpret_cast<__half2*>(d0)[1] = hp1;
    if (HILO) {
        __half l[4];
        #pragma unroll
        for (int j = 0; j < 4; ++j) l[j] = __float2half(vs[j] - __half2float(h[j]));
        reinterpret_cast<__half2*>(d0 + K)[0] = __half2(l[0], l[1]);
        reinterpret_cast<__half2*>(d0 + K)[1] = __half2(l[2], l[3]);
    } else {
        reinterpret_cast<__half2*>(d0 + K)[0] = hp0;
        reinterpret_cast<__half2*>(d0 + K)[1] = hp1;
    }
}

// ---------------- V transpose fp16 -> fp16 (B-order, single) -----------------
__global__ void vtrans_kernel(const __half* __restrict__ Vh, __half* __restrict__ VB)
{
    __shared__ __half t[32][34];
    const int b = blockIdx.z;
    const int n0 = blockIdx.x * 32, e0 = blockIdx.y * 32;
    const int tx = threadIdx.x, ty = threadIdx.y;
    const __half* src = Vh + (size_t)b * SEQ * EMBED;
    #pragma unroll
    for (int i = 0; i < 4; ++i)
        t[ty + 8 * i][tx] = src[(size_t)(n0 + ty + 8 * i) * EMBED + e0 + tx];
    __syncthreads();
    __half* dst = VB + (size_t)b * EMBED * SEQ;
    #pragma unroll
    for (int i = 0; i < 4; ++i)
        dst[(size_t)(e0 + ty + 8 * i) * SEQ + n0 + tx] = t[tx][ty + 8 * i];
}

// ---------------- softmax -> fp16 probs (single term) ------------------------
__global__ void softmax_pa_kernel(const float* __restrict__ s, __half* __restrict__ PA)
{
    __shared__ float row[SEQ];
    __shared__ float red[8];
    const int tid = threadIdx.x;
    const float4* p4 = reinterpret_cast<const float4*>(s + (size_t)blockIdx.x * SEQ);
    float4* r4 = reinterpret_cast<float4*>(row);

    float lmax = -3.4e38f;
    #pragma unroll
    for (int it = 0; it < 2; ++it) {
        const float4 t = p4[tid + it * 256];
        r4[tid + it * 256] = t;
        lmax = fmaxf(lmax, fmaxf(fmaxf(t.x, t.y), fmaxf(t.z, t.w)));
    }
    #pragma unroll
    for (int o = 16; o; o >>= 1) lmax = fmaxf(lmax, __shfl_xor_sync(0xffffffffu, lmax, o));
    if ((tid & 31) == 0) red[tid >> 5] = lmax;
    __syncthreads();
    const float rmax = fmaxf(fmaxf(fmaxf(red[0], red[1]), fmaxf(red[2], red[3])),
                             fmaxf(fmaxf(red[4], red[5]), fmaxf(red[6], red[7])));
    __syncthreads();

    float lsum = 0.0f;
    #pragma unroll
    for (int it = 0; it < 2; ++it) {
        float4 t = r4[tid + it * 256];
        t.x = expf(t.x - rmax); t.y = expf(t.y - rmax);
        t.z = expf(t.z - rmax); t.w = expf(t.w - rmax);
        r4[tid + it * 256] = t;
        lsum += (t.x + t.y) + (t.z + t.w);
    }
    #pragma unroll
    for (int o = 16; o; o >>= 1) lsum += __shfl_xor_sync(0xffffffffu, lsum, o);
    if ((tid & 31) == 0) red[tid >> 5] = lsum;
    __syncthreads();
    const float inv = 1.0f / (((red[0] + red[1]) + (red[2] + red[3])) +
                              ((red[4] + red[5]) + (red[6] + red[7])));

    __half* pa = PA + (size_t)blockIdx.x * SEQ;
    #pragma unroll
    for (int it = 0; it < 2; ++it) {
        float4 t = r4[tid + it * 256];
        const int idx = (tid + it * 256) * 4;
        __half2 hp0(__float2half(t.x * inv), __float2half(t.y * inv));
        __half2 hp1(__float2half(t.z * inv), __float2half(t.w * inv));
        reinterpret_cast<__half2*>(pa + idx)[0] = hp0;
        reinterpret_cast<__half2*>(pa + idx)[1] = hp1;
    }
}

// -----------------------------------------------------------------------------
extern "C" void kernel_launch(void* const* d_in, const int* in_sizes, int n_in,
                              void* d_out, int out_size)
{
    const float* x = (const float*)d_in[0];
    const float* W = (const float*)d_in[1];
    const float* b = (const float*)d_in[2];
    float* out = (float*)d_out;

    float *sc;
    __half *Vh, *A1, *B1, *QA, *KB, *VB, *PA;
    { void* p; cudaGetSymbolAddress(&p, g_Vh);     Vh = (__half*)p; }
    { void* p; cudaGetSymbolAddress(&p, g_scores); sc = (float*)p; }
    { void* p; cudaGetSymbolAddress(&p, g_A1); A1 = (__half*)p; }
    { void* p; cudaGetSymbolAddress(&p, g_B1); B1 = (__half*)p; }
    { void* p; cudaGetSymbolAddress(&p, g_QA); QA = (__half*)p; }
    { void* p; cudaGetSymbolAddress(&p, g_KB); KB = (__half*)p; }
    { void* p; cudaGetSymbolAddress(&p, g_VB); VB = (__half*)p; }
    { void* p; cudaGetSymbolAddress(&p, g_PA); PA = (__half*)p; }

    cudaFuncSetAttribute(mma_gemm<0>, cudaFuncAttributeMaxDynamicSharedMemorySize, SMEM_B);
    cudaFuncSetAttribute(mma_gemm<1>, cudaFuncAttributeMaxDynamicSharedMemorySize, SMEM_B);

    const long long MN = (long long)BATCH * SEQ;   // 16384

    // input splits: x -> A1 fp16 [hi|lo], W -> B1 fp16 [hi|hi]
    split_kernel<true ><<<(unsigned)((MN * EMBED / 4 + 255) / 256), 256>>>(
        x, A1, EMBED, MN * EMBED / 4);
    split_kernel<false><<<(unsigned)(((long long)QKVD * EMBED / 4 + 255) / 256), 256>>>(
        W, B1, EMBED, (long long)QKVD * EMBED / 4);

    // GEMM1 (fused): qkv = x @ W^T + b  (Keff=2048, fp16 2-term)
    //   -> QA fp16 (single), KB fp16 (single), Vh fp16 (single)
    mma_gemm<1><<<dim3(QKVD / 128, (unsigned)(MN / 128), 1), 256, SMEM_B>>>(
        A1, B1, b, nullptr, QA, KB, Vh,
        2 * EMBED, 0, 0, 0, 0, 1.0f);

    // V transpose -> fp16 single
    vtrans_kernel<<<dim3(SEQ / 32, EMBED / 32, BATCH), dim3(32, 8)>>>(Vh, VB);

    // GEMM2: scores = Q @ K^T / 32   (per batch M=N=2048, Keff=1024, fp16 single)
    mma_gemm<0><<<dim3(SEQ / 128, SEQ / 128, BATCH), 256, SMEM_B>>>(
        QA, KB, nullptr, sc, nullptr, nullptr, nullptr,
        EMBED, SEQ,
        (long long)SEQ * EMBED, (long long)SEQ * EMBED, (long long)SEQ * SEQ,
        0.03125f);

    // softmax -> fp16 probs (single term)
    softmax_pa_kernel<<<BATCH * SEQ, 256>>>(sc, PA);

    // GEMM3: out = P @ V   (per batch M=2048, N=1024, Keff=2048, fp16 single)
    mma_gemm<0><<<dim3(EMBED / 128, SEQ / 128, BATCH), 256, SMEM_B>>>(
        PA, VB, nullptr, out, nullptr, nullptr, nullptr,
        SEQ, EMBED,
        (long long)SEQ * SEQ, (long long)EMBED * SEQ, (long long)SEQ * EMBED,
        1.0f);
}

// round 12
// speedup vs baseline: 3.1783x; 1.3711x over previous
#include <cuda_runtime.h>
#include <cuda_bf16.h>
#include <cuda_fp16.h>
#include <math.h>
#include <stdint.h>

#define BATCH   8
#define SEQ     2048
#define EMBED   1024
#define QKVD    3072

// ---------------- scratch (device globals; no allocs allowed) ---------------
__device__ __half g_Vh    [(size_t)BATCH * SEQ * EMBED];   // fp16 V (row-major)
__device__ float  g_scores[(size_t)BATCH * SEQ * SEQ];
__device__ __half g_A1[(size_t)BATCH * SEQ * EMBED];       // x fp16 (single)
__device__ __half g_B1[(size_t)QKVD * EMBED];              // W fp16 (single)
__device__ __half g_QA[(size_t)BATCH * SEQ * EMBED];       // Q fp16 (single)
__device__ __half g_KB[(size_t)BATCH * SEQ * EMBED];       // K fp16 (single)
__device__ __half g_VB[(size_t)BATCH * EMBED * SEQ];       // V^T fp16 (single)
__device__ __half g_PA[(size_t)BATCH * SEQ * SEQ];         // probs fp16 (single)

// ---------------- asm helpers ------------------------------------------------
__device__ __forceinline__ uint32_t smem_u32(const void* p) {
    uint32_t a;
    asm("{ .reg .u64 t; cvta.to.shared.u64 t, %1; cvt.u32.u64 %0, t; }" : "=r"(a) : "l"(p));
    return a;
}
#define CP_ASYNC16(dst, src) \
    asm volatile("cp.async.cg.shared.global [%0], [%1], 16;" :: "r"(dst), "l"(src))
#define CP_COMMIT() asm volatile("cp.async.commit_group;" ::: "memory")
#define CP_WAIT1()  asm volatile("cp.async.wait_group 1;"  ::: "memory")
#define LDMX4(r, addr) \
    asm volatile("ldmatrix.sync.aligned.m8n8.x4.shared.b16 {%0,%1,%2,%3}, [%4];" \
        : "=r"((r)[0]), "=r"((r)[1]), "=r"((r)[2]), "=r"((r)[3]) : "r"(addr))
#define MMA16816_F16(d, a, b) \
    asm volatile("mma.sync.aligned.m16n8k16.row.col.f32.f16.f16.f32 " \
        "{%0,%1,%2,%3}, {%4,%5,%6,%7}, {%8,%9}, {%0,%1,%2,%3};" \
        : "+f"((d)[0]), "+f"((d)[1]), "+f"((d)[2]), "+f"((d)[3]) \
        : "r"((a)[0]), "r"((a)[1]), "r"((a)[2]), "r"((a)[3]), "r"((b)[0]), "r"((b)[1]))

// ---------------- tensor-core GEMM -------------------------------------------
// C[m,n] = alpha * sum_k A[m,k] B[n,k]   (A, B row-major fp16, K-major)
// CTA tile 128x128, K-chunk 64, 3-stage cp.async, single-sync multistage loop.
// 256 threads = 8 warps (2m x 4n), warp tile 64x32, mma.m16n8k16 fp16 -> fp32.
// MODE 0: plain epilogue (alpha scale) -> fp32 C
// MODE 1: fused qkv epilogue (bias + single-fp16 writes to QA/KB/Vh)
#define LDT     72                       // smem row pitch in halves (144 B)
#define ATILE_H (128 * LDT)
#define STAGE_H (2 * ATILE_H)            // A+B tile per stage (halves)
#define NSTAGE  3
#define SMEM_B  (NSTAGE * STAGE_H * 2)   // 110592 bytes

__device__ __forceinline__ void load_chunk(uint32_t sb, int stage,
    const __half* __restrict__ Ag, const __half* __restrict__ Bg,
    int K, int k0, int tid)
{
    const int r = tid >> 1;
    const int c = (tid & 1) * 32;
    const uint32_t base = sb + (uint32_t)stage * (STAGE_H * 2) + (r * LDT + c) * 2;
    const __half* as = Ag + (size_t)r * K + k0 + c;
    const __half* bs = Bg + (size_t)r * K + k0 + c;
    #pragma unroll
    for (int i = 0; i < 4; ++i) CP_ASYNC16(base + i * 16, as + i * 8);
    #pragma unroll
    for (int i = 0; i < 4; ++i) CP_ASYNC16(base + ATILE_H * 2 + i * 16, bs + i * 8);
}

template<int MODE>
__global__ void __launch_bounds__(256, 2) mma_gemm(
    const __half* __restrict__ A, const __half* __restrict__ B,
    const float* __restrict__ bias, float* __restrict__ C,
    __half* __restrict__ QA, __half* __restrict__ KB, __half* __restrict__ Vh,
    int K, int ldc, long long sA, long long sB, long long sC, float alpha)
{
    extern __shared__ char smem[];
    const uint32_t sb = smem_u32(smem);
    const int tid = threadIdx.x;
    const int lane = tid & 31;
    const int wid = tid >> 5;
    const int wm = (wid & 1) * 64;
    const int wn = (wid >> 1) * 32;

    const __half* Ag = A + blockIdx.z * sA + (size_t)(blockIdx.y * 128) * K;
    const __half* Bg = B + blockIdx.z * sB + (size_t)(blockIdx.x * 128) * K;

    const int ar = (lane & 7) + ((lane >> 3) & 1) * 8;
    const int ak = (lane >> 4) * 8;
    const int bn = (lane & 7) + ((lane >> 4) & 1) * 8;
    const int bk = ((lane >> 3) & 1) * 8;

    float acc[4][4][4];
    #pragma unroll
    for (int i = 0; i < 4; ++i)
        #pragma unroll
        for (int j = 0; j < 4; ++j)
            #pragma unroll
            for (int q = 0; q < 4; ++q) acc[i][j][q] = 0.0f;

    const int nch = K / 64;
    load_chunk(sb, 0, Ag, Bg, K, 0, tid);  CP_COMMIT();
    load_chunk(sb, 1, Ag, Bg, K, 64, tid); CP_COMMIT();

    for (int ch = 0; ch < nch; ++ch) {
        const int stage = ch % NSTAGE;
        CP_WAIT1();              // chunk ch resident
        __syncthreads();         // publish cp.async writes; free stage (ch-1)%3

        if (ch + 2 < nch) load_chunk(sb, (ch + 2) % NSTAGE, Ag, Bg, K, (ch + 2) * 64, tid);
        CP_COMMIT();

        const uint32_t abase = sb + (uint32_t)stage * (STAGE_H * 2);
        const uint32_t bbase = abase + ATILE_H * 2;
        #pragma unroll
        for (int s = 0; s < 4; ++s) {
            uint32_t a[4][4];
            #pragma unroll
            for (int mf = 0; mf < 4; ++mf)
                LDMX4(a[mf], abase + ((wm + mf * 16 + ar) * LDT + s * 16 + ak) * 2);
            uint32_t b[2][4];
            #pragma unroll
            for (int n2 = 0; n2 < 2; ++n2)
                LDMX4(b[n2], bbase + ((wn + n2 * 16 + bn) * LDT + s * 16 + bk) * 2);
            #pragma unroll
            for (int mf = 0; mf < 4; ++mf)
                #pragma unroll
                for (int nf = 0; nf < 4; ++nf)
                    MMA16816_F16(acc[mf][nf], a[mf], &b[nf >> 1][(nf & 1) * 2]);
        }
    }

    // ---------------- epilogue ----------------
    const int g  = lane >> 2;
    const int tg = lane & 3;

    if (MODE == 0) {
        float* Cg = C + blockIdx.z * sC;
        #pragma unroll
        for (int mf = 0; mf < 4; ++mf) {
            const int row0 = blockIdx.y * 128 + wm + mf * 16 + g;
            #pragma unroll
            for (int nf = 0; nf < 4; ++nf) {
                const int col = blockIdx.x * 128 + wn + nf * 8 + tg * 2;
                float2 v0 = make_float2(acc[mf][nf][0] * alpha, acc[mf][nf][1] * alpha);
                float2 v1 = make_float2(acc[mf][nf][2] * alpha, acc[mf][nf][3] * alpha);
                *reinterpret_cast<float2*>(Cg + (size_t)row0 * ldc + col) = v0;
                *reinterpret_cast<float2*>(Cg + (size_t)(row0 + 8) * ldc + col) = v1;
            }
        }
    } else {
        const int cblk = blockIdx.x * 128;
        const int region = cblk >> 10;               // 0=Q 1=K 2=V
        __half* dst = (region == 0) ? QA : (region == 1) ? KB : Vh;
        #pragma unroll
        for (int mf = 0; mf < 4; ++mf) {
            const int row0 = blockIdx.y * 128 + wm + mf * 16 + g;
            #pragma unroll
            for (int nf = 0; nf < 4; ++nf) {
                const int gcol = cblk + wn + nf * 8 + tg * 2;
                const float2 bb = *reinterpret_cast<const float2*>(bias + gcol);
                const int lcol = gcol & 1023;
                #pragma unroll
                for (int h = 0; h < 2; ++h) {
                    const int r = row0 + h * 8;
                    const __half2 hp(__float2half(acc[mf][nf][h * 2 + 0] + bb.x),
                                     __float2half(acc[mf][nf][h * 2 + 1] + bb.y));
                    *reinterpret_cast<__half2*>(dst + (size_t)r * EMBED + lcol) = hp;
                }
            }
        }
    }
}

// ---------------- fp32 -> fp16 convert ----------------------------------------
__global__ void cvt_kernel(const float* __restrict__ src, __half* __restrict__ dst,
                           long long nvec)
{
    long long i = blockIdx.x * (long long)blockDim.x + threadIdx.x;
    if (i >= nvec) return;
    const float4 v = *reinterpret_cast<const float4*>(src + i * 4);
    __half2 h0(__float2half(v.x), __float2half(v.y));
    __half2 h1(__float2half(v.z), __float2half(v.w));
    reinterpret_cast<__half2*>(dst + i * 4)[0] = h0;
    reinterpret_cast<__half2*>(dst + i * 4)[1] = h1;
}

// ---------------- V transpose fp16 -> fp16 (B-order, single) -----------------
__global__ void vtrans_kernel(const __half* __restrict__ Vh, __half* __restrict__ VB)
{
    __shared__ __half t[32][34];
    const int b = blockIdx.z;
    const int n0 = blockIdx.x * 32, e0 = blockIdx.y * 32;
    const int tx = threadIdx.x, ty = threadIdx.y;
    const __half* src = Vh + (size_t)b * SEQ * EMBED;
    #pragma unroll
    for (int i = 0; i < 4; ++i)
        t[ty + 8 * i][tx] = src[(size_t)(n0 + ty + 8 * i) * EMBED + e0 + tx];
    __syncthreads();
    __half* dst = VB + (size_t)b * EMBED * SEQ;
    #pragma unroll
    for (int i = 0; i < 4; ++i)
        dst[(size_t)(e0 + ty + 8 * i) * SEQ + n0 + tx] = t[tx][ty + 8 * i];
}

// ---------------- softmax -> fp16 probs (single term) ------------------------
__global__ void softmax_pa_kernel(const float* __restrict__ s, __half* __restrict__ PA)
{
    __shared__ float row[SEQ];
    __shared__ float red[8];
    const int tid = threadIdx.x;
    const float4* p4 = reinterpret_cast<const float4*>(s + (size_t)blockIdx.x * SEQ);
    float4* r4 = reinterpret_cast<float4*>(row);

    float lmax = -3.4e38f;
    #pragma unroll
    for (int it = 0; it < 2; ++it) {
        const float4 t = p4[tid + it * 256];
        r4[tid + it * 256] = t;
        lmax = fmaxf(lmax, fmaxf(fmaxf(t.x, t.y), fmaxf(t.z, t.w)));
    }
    #pragma unroll
    for (int o = 16; o; o >>= 1) lmax = fmaxf(lmax, __shfl_xor_sync(0xffffffffu, lmax, o));
    if ((tid & 31) == 0) red[tid >> 5] = lmax;
    __syncthreads();
    const float rmax = fmaxf(fmaxf(fmaxf(red[0], red[1]), fmaxf(red[2], red[3])),
                             fmaxf(fmaxf(red[4], red[5]), fmaxf(red[6], red[7])));
    __syncthreads();

    float lsum = 0.0f;
    #pragma unroll
    for (int it = 0; it < 2; ++it) {
        float4 t = r4[tid + it * 256];
        t.x = expf(t.x - rmax); t.y = expf(t.y - rmax);
        t.z = expf(t.z - rmax); t.w = expf(t.w - rmax);
        r4[tid + it * 256] = t;
        lsum += (t.x + t.y) + (t.z + t.w);
    }
    #pragma unroll
    for (int o = 16; o; o >>= 1) lsum += __shfl_xor_sync(0xffffffffu, lsum, o);
    if ((tid & 31) == 0) red[tid >> 5] = lsum;
    __syncthreads();
    const float inv = 1.0f / (((red[0] + red[1]) + (red[2] + red[3])) +
                              ((red[4] + red[5]) + (red[6] + red[7])));

    __half* pa = PA + (size_t)blockIdx.x * SEQ;
    #pragma unroll
    for (int it = 0; it < 2; ++it) {
        float4 t = r4[tid + it * 256];
        const int idx = (tid + it * 256) * 4;
        __half2 hp0(__float2half(t.x * inv), __float2half(t.y * inv));
        __half2 hp1(__float2half(t.z * inv), __float2half(t.w * inv));
        reinterpret_cast<__half2*>(pa + idx)[0] = hp0;
        reinterpret_cast<__half2*>(pa + idx)[1] = hp1;
    }
}

// -----------------------------------------------------------------------------
extern "C" void kernel_launch(void* const* d_in, const int* in_sizes, int n_in,
                              void* d_out, int out_size)
{
    const float* x = (const float*)d_in[0];
    const float* W = (const float*)d_in[1];
    const float* b = (const float*)d_in[2];
    float* out = (float*)d_out;

    float *sc;
    __half *Vh, *A1, *B1, *QA, *KB, *VB, *PA;
    { void* p; cudaGetSymbolAddress(&p, g_Vh);     Vh = (__half*)p; }
    { void* p; cudaGetSymbolAddress(&p, g_scores); sc = (float*)p; }
    { void* p; cudaGetSymbolAddress(&p, g_A1); A1 = (__half*)p; }
    { void* p; cudaGetSymbolAddress(&p, g_B1); B1 = (__half*)p; }
    { void* p; cudaGetSymbolAddress(&p, g_QA); QA = (__half*)p; }
    { void* p; cudaGetSymbolAddress(&p, g_KB); KB = (__half*)p; }
    { void* p; cudaGetSymbolAddress(&p, g_VB); VB = (__half*)p; }
    { void* p; cudaGetSymbolAddress(&p, g_PA); PA = (__half*)p; }

    cudaFuncSetAttribute(mma_gemm<0>, cudaFuncAttributeMaxDynamicSharedMemorySize, SMEM_B);
    cudaFuncSetAttribute(mma_gemm<1>, cudaFuncAttributeMaxDynamicSharedMemorySize, SMEM_B);

    const long long MN = (long long)BATCH * SEQ;   // 16384

    // input converts: x -> A1 fp16, W -> B1 fp16
    cvt_kernel<<<(unsigned)((MN * EMBED / 4 + 255) / 256), 256>>>(
        x, A1, MN * EMBED / 4);
    cvt_kernel<<<(unsigned)(((long long)QKVD * EMBED / 4 + 255) / 256), 256>>>(
        W, B1, (long long)QKVD * EMBED / 4);

    // GEMM1 (fused): qkv = x_hi @ W_hi^T + b  (Keff=1024, fp16 single)
    //   -> QA fp16, KB fp16, Vh fp16
    mma_gemm<1><<<dim3(QKVD / 128, (unsigned)(MN / 128), 1), 256, SMEM_B>>>(
        A1, B1, b, nullptr, QA, KB, Vh,
        EMBED, 0, 0, 0, 0, 1.0f);

    // V transpose -> fp16 single
    vtrans_kernel<<<dim3(SEQ / 32, EMBED / 32, BATCH), dim3(32, 8)>>>(Vh, VB);

    // GEMM2: scores = Q @ K^T / 32   (per batch M=N=2048, Keff=1024, fp16 single)
    mma_gemm<0><<<dim3(SEQ / 128, SEQ / 128, BATCH), 256, SMEM_B>>>(
        QA, KB, nullptr, sc, nullptr, nullptr, nullptr,
        EMBED, SEQ,
        (long long)SEQ * EMBED, (long long)SEQ * EMBED, (long long)SEQ * SEQ,
        0.03125f);

    // softmax -> fp16 probs (single term)
    softmax_pa_kernel<<<BATCH * SEQ, 256>>>(sc, PA);

    // GEMM3: out = P @ V   (per batch M=2048, N=1024, Keff=2048, fp16 single)
    mma_gemm<0><<<dim3(EMBED / 128, SEQ / 128, BATCH), 256, SMEM_B>>>(
        PA, VB, nullptr, out, nullptr, nullptr, nullptr,
        SEQ, EMBED,
        (long long)SEQ * SEQ, (long long)EMBED * SEQ, (long long)SEQ * EMBED,
        1.0f);
}